// round 15
// baseline (speedup 1.0000x reference)
#include <cuda_runtime.h>
#include <cuda_bf16.h>
#include <cuda_fp16.h>
#include <stdint.h>
#include <math.h>

#define BSZ   32
#define LSEQ  1024
#define DIM   512
#define MTOT  (BSZ*LSEQ)          // 32768
#define GDIM  2048                // 4*DIM

// =================== scratch (device globals) ================================
__device__ __align__(128) __nv_bfloat16 g_aHi[(size_t)MTOT*DIM];
__device__ __align__(128) __nv_bfloat16 g_aLo[(size_t)MTOT*DIM];
__device__ __align__(128) __nv_bfloat16 g_bHi[(size_t)MTOT*DIM];
__device__ __align__(128) __nv_bfloat16 g_bLo[(size_t)MTOT*DIM];
__device__ __align__(128) __nv_bfloat16 g_wcHi[3][(size_t)3*DIM*DIM];   // [layer][tap*512+n][k]
__device__ __align__(128) __nv_bfloat16 g_wcLo[3][(size_t)3*DIM*DIM];
__device__ __align__(128) __nv_bfloat16 g_wgHi[2][(size_t)GDIM*DIM];    // [dir][n][k]
__device__ __align__(128) __nv_bfloat16 g_wgLo[2][(size_t)GDIM*DIM];
__device__ __align__(128) __half g_wrHi[2][(size_t)GDIM*DIM];           // recurrent W fp16 (hi only)
__device__ float g_gpre[2][(size_t)MTOT*GDIM];   // [dir][ (t*2048 + col)*32 + b ]
__device__ __align__(128) __half g_h16[2][2][BSZ*DIM];  // [parity][dir][b*512+d]
__device__ float g_alpha[3][DIM];
__device__ float g_beta[3][DIM];
__device__ __align__(1024) unsigned g_bar[2][256];    // monotonic, dirs 1KB apart

// =================== primitives ===============================================
__device__ __forceinline__ uint32_t smem_to_u32(const void* p) {
    uint32_t a;
    asm("{ .reg .u64 t; cvta.to.shared.u64 t, %1; cvt.u32.u64 %0, t; }" : "=r"(a) : "l"(p));
    return a;
}
#define LDSM_X4(r0, r1, r2, r3, addr) \
    asm volatile("ldmatrix.sync.aligned.m8n8.x4.shared.b16 {%0,%1,%2,%3}, [%4];" \
        : "=r"(r0), "=r"(r1), "=r"(r2), "=r"(r3) : "r"(addr))
#define MMA16816(c, a, b) \
    asm volatile("mma.sync.aligned.m16n8k16.row.col.f32.bf16.bf16.f32 " \
        "{%0,%1,%2,%3}, {%4,%5,%6,%7}, {%8,%9}, {%0,%1,%2,%3};" \
        : "+f"((c)[0]), "+f"((c)[1]), "+f"((c)[2]), "+f"((c)[3]) \
        : "r"((a)[0]), "r"((a)[1]), "r"((a)[2]), "r"((a)[3]), \
          "r"((b)[0]), "r"((b)[1]))
#define MMAF16(c, a, b) \
    asm volatile("mma.sync.aligned.m16n8k16.row.col.f32.f16.f16.f32 " \
        "{%0,%1,%2,%3}, {%4,%5,%6,%7}, {%8,%9}, {%0,%1,%2,%3};" \
        : "+f"((c)[0]), "+f"((c)[1]), "+f"((c)[2]), "+f"((c)[3]) \
        : "r"((a)[0]), "r"((a)[1]), "r"((a)[2]), "r"((a)[3]), \
          "r"((b)[0]), "r"((b)[1]))
// cp.async 16B with zero-fill: src_size=0 -> all-zero fill, 16 -> full copy
#define CP16(dst, src) \
    asm volatile("cp.async.cg.shared.global [%0], [%1], 16;" \
        :: "r"(dst), "l"(src) : "memory")
#define CP16Z(dst, src, sz) \
    asm volatile("cp.async.cg.shared.global [%0], [%1], 16, %2;" \
        :: "r"(dst), "l"(src), "r"(sz) : "memory")
#define CP_COMMIT() asm volatile("cp.async.commit_group;" ::: "memory")
#define CP_WAIT0()  asm volatile("cp.async.wait_group 0;" ::: "memory")

__device__ __forceinline__ float tanh_fast_(float x) {
    float y;
    asm("tanh.approx.f32 %0, %1;" : "=f"(y) : "f"(x));
    return y;
}
__device__ __forceinline__ float sigmoid_fast_(float x) {
    return fmaf(tanh_fast_(0.5f * x), 0.5f, 0.5f);
}
__device__ __forceinline__ unsigned bar_arrive_(unsigned* arr) {
    unsigned prev;
    asm volatile("atom.release.gpu.global.add.u32 %0, [%1], 1;"
                 : "=r"(prev) : "l"(arr) : "memory");
    return prev;
}
__device__ __forceinline__ void bar_wait_(unsigned* arr, unsigned tgt) {
    unsigned v;
    do {
        asm volatile("ld.acquire.gpu.global.u32 %0, [%1];" : "=r"(v) : "l"(arr));
    } while (v < tgt);
}

// =================== barrier reset (determinism across graph replays) ========
__global__ void bar_reset_kernel()
{
    g_bar[threadIdx.x >> 8][threadIdx.x & 255] = 0u;
}

// =================== BN fold =================================================
__global__ void bnprep_kernel(
    const float* __restrict__ b1, const float* __restrict__ s1, const float* __restrict__ o1,
    const float* __restrict__ m1, const float* __restrict__ v1,
    const float* __restrict__ b2, const float* __restrict__ s2, const float* __restrict__ o2,
    const float* __restrict__ m2, const float* __restrict__ v2,
    const float* __restrict__ b3, const float* __restrict__ s3, const float* __restrict__ o3,
    const float* __restrict__ m3, const float* __restrict__ v3)
{
    int i = threadIdx.x;
    if (i < DIM) {
        float g;
        g = s1[i] * rsqrtf(v1[i] + 1e-5f); g_alpha[0][i] = g; g_beta[0][i] = (b1[i] - m1[i]) * g + o1[i];
        g = s2[i] * rsqrtf(v2[i] + 1e-5f); g_alpha[1][i] = g; g_beta[1][i] = (b2[i] - m2[i]) * g + o2[i];
        g = s3[i] * rsqrtf(v3[i] + 1e-5f); g_alpha[2][i] = g; g_beta[2][i] = (b3[i] - m3[i]) * g + o3[i];
    }
}

// =================== weight prep (coalesced 32x32 transposes) =================
__global__ void wprep_conv_kernel(const float* __restrict__ c1,
                                  const float* __restrict__ c2,
                                  const float* __restrict__ c3)
{
    __shared__ float tile[32][33];
    const int tx = threadIdx.x, ty = threadIdx.y;
    const int k0 = blockIdx.x * 32, n0 = blockIdx.y * 32;
    const int layer = blockIdx.z / 3, tap = blockIdx.z % 3;
    const float* W = (layer == 0) ? c1 : ((layer == 1) ? c2 : c3);
    #pragma unroll
    for (int i = 0; i < 4; i++)
        tile[ty + i * 8][tx] = W[(size_t)(tap * DIM + k0 + ty + i * 8) * DIM + n0 + tx];
    __syncthreads();
    #pragma unroll
    for (int i = 0; i < 4; i++) {
        int n = n0 + ty + i * 8;
        float v = tile[tx][ty + i * 8];
        __nv_bfloat16 h = __float2bfloat16(v);
        __nv_bfloat16 l = __float2bfloat16(v - __bfloat162float(h));
        g_wcHi[layer][(size_t)(tap * DIM + n) * DIM + k0 + tx] = h;
        g_wcLo[layer][(size_t)(tap * DIM + n) * DIM + k0 + tx] = l;
    }
}
__global__ void wprep_gate_kernel(const float* __restrict__ Wf,
                                  const float* __restrict__ Wb)
{
    __shared__ float tile[32][33];
    const int tx = threadIdx.x, ty = threadIdx.y;
    const int k0 = blockIdx.x * 32, n0 = blockIdx.y * 32;
    const int dir = blockIdx.z;
    const float* W = dir ? Wb : Wf;
    #pragma unroll
    for (int i = 0; i < 4; i++)
        tile[ty + i * 8][tx] = W[(size_t)(k0 + ty + i * 8) * GDIM + n0 + tx];
    __syncthreads();
    #pragma unroll
    for (int i = 0; i < 4; i++) {
        int n = n0 + ty + i * 8;
        float v = tile[tx][ty + i * 8];
        __nv_bfloat16 h = __float2bfloat16(v);
        __nv_bfloat16 l = __float2bfloat16(v - __bfloat162float(h));
        g_wgHi[dir][(size_t)n * DIM + k0 + tx] = h;
        g_wgLo[dir][(size_t)n * DIM + k0 + tx] = l;
    }
}
__global__ void wprep_rec_kernel(const float* __restrict__ Wf,
                                 const float* __restrict__ Wb)
{
    __shared__ float tile[32][33];
    const int tx = threadIdx.x, ty = threadIdx.y;
    const int k0 = blockIdx.x * 32, n0 = blockIdx.y * 32;
    const int dir = blockIdx.z;
    const float* W = dir ? Wb : Wf;
    #pragma unroll
    for (int i = 0; i < 4; i++)
        tile[ty + i * 8][tx] = W[(size_t)(DIM + k0 + ty + i * 8) * GDIM + n0 + tx];
    __syncthreads();
    #pragma unroll
    for (int i = 0; i < 4; i++) {
        int n = n0 + ty + i * 8;
        g_wrHi[dir][(size_t)n * DIM + k0 + tx] = __float2half_rn(tile[tx][ty + i * 8]);
    }
}

// =================== embedding -> bf16 hi/lo =================================
__global__ void embed_kernel(const int* __restrict__ x, const float* __restrict__ ew)
{
    int m = blockIdx.x;
    int tok = x[m];
    int j = threadIdx.x;
    float4 v = ((const float4*)(ew + (size_t)tok * DIM))[j];
    float f[4] = {v.x, v.y, v.z, v.w};
    __nv_bfloat16 h[4], l[4];
    #pragma unroll
    for (int i = 0; i < 4; i++) {
        h[i] = __float2bfloat16(f[i]);
        l[i] = __float2bfloat16(f[i] - __bfloat162float(h[i]));
    }
    *(uint2*)(g_aHi + (size_t)m * DIM + j * 4) = *(uint2*)h;
    *(uint2*)(g_aLo + (size_t)m * DIM + j * 4) = *(uint2*)l;
}

// =================== bf16 mma.sync GEMM — cp.async staging ====================
__global__ void __launch_bounds__(256, 2) mma_gemm_kernel(
    const __nv_bfloat16* __restrict__ Ahi, const __nv_bfloat16* __restrict__ Alo,
    const __nv_bfloat16* __restrict__ BwHi, const __nv_bfloat16* __restrict__ BwLo,
    int taps, int layer, int bperm,
    __nv_bfloat16* __restrict__ outHi, __nv_bfloat16* __restrict__ outLo,
    const float* __restrict__ biasA, const float* __restrict__ biasB,
    float* __restrict__ gout)
{
    extern __shared__ char smem[];
    const int tid = threadIdx.x;
    const int lane = tid & 31, wid = tid >> 5;
    const int wm = wid & 3, wn = wid >> 2;
    const int m0 = blockIdx.x * 128, n0 = blockIdx.y * 128;
    const int t0 = m0 & (LSEQ - 1);
    const int tb4 = blockIdx.x * 4;
    const int dz = blockIdx.z;
    const uint32_t sb = smem_to_u32(smem);

    if (bperm) {
        BwHi += (size_t)dz * GDIM * DIM;
        BwLo += (size_t)dz * GDIM * DIM;
        gout += (size_t)dz * MTOT * GDIM;
    }
    const float* bias = dz ? biasB : biasA;

    const int off0  = taps >> 1;
    const int arows = 128 + (taps - 1);

    float acc[2][8][4];
    #pragma unroll
    for (int a = 0; a < 2; a++)
        #pragma unroll
        for (int b = 0; b < 8; b++)
            #pragma unroll
            for (int c = 0; c < 4; c++) acc[a][b][c] = 0.f;

    // async copies: each thread issues LDGSTS, no register round trip
    #define DO_COPY_A(SLICE) do { \
        const int _kb = (SLICE) << 6; \
        const int _tot = arows * 8; \
        for (int _i = tid; _i < _tot; _i += 256) { \
            int _r = _i >> 3, _c8 = (_i & 7) << 3; \
            uint32_t _off = (uint32_t)(_r * 128) + (((uint32_t)_c8 * 2) ^ (((uint32_t)_r & 7) << 4)); \
            if (bperm) { \
                size_t _ga = (size_t)(((_r & 31) << 10) + tb4 + (_r >> 5)) * DIM + _kb + _c8; \
                CP16(sb + _off, Ahi + _ga); \
                CP16(sb + 16640 + _off, Alo + _ga); \
            } else { \
                int _tl = t0 + _r - off0; \
                int _ok = (_tl >= 0 && _tl < LSEQ); \
                size_t _ga = _ok ? ((size_t)(m0 + _r - off0) * DIM + _kb + _c8) : 0; \
                int _sz = _ok ? 16 : 0; \
                CP16Z(sb + _off, Ahi + _ga, _sz); \
                CP16Z(sb + 16640 + _off, Alo + _ga, _sz); \
            } \
        } \
    } while (0)

    #define DO_COPY_B(IDX, ST) do { \
        const int _sl = (IDX) / taps, _tp = (IDX) % taps; \
        const int _kb = _sl << 6; \
        const int _rbase = (taps == 3 ? _tp * DIM : 0) + n0; \
        uint32_t _bp = sb + 33280 + (ST) * 32768; \
        for (int _i = tid; _i < 1024; _i += 256) { \
            int _r = _i >> 3, _c8 = (_i & 7) << 3; \
            uint32_t _off = (uint32_t)(_r * 128) + (((uint32_t)_c8 * 2) ^ (((uint32_t)_r & 7) << 4)); \
            size_t _ga = (size_t)(_rbase + _r) * DIM + _kb + _c8; \
            CP16(_bp + _off, BwHi + _ga); \
            CP16(_bp + 16384 + _off, BwLo + _ga); \
        } \
    } while (0)

    const int NB = 8 * taps;
    DO_COPY_A(0);
    DO_COPY_B(0, 0);
    CP_COMMIT();
    CP_WAIT0();
    __syncthreads();

    for (int idx = 0; idx < NB; idx++) {
        const int tap = idx % taps;
        const int bsel = idx & 1;
        const bool lastTap = (tap == taps - 1);

        if (idx + 1 < NB) { DO_COPY_B(idx + 1, bsel ^ 1); CP_COMMIT(); }

        const uint32_t aHiB = sb;
        const uint32_t aLoB = sb + 16640;
        const uint32_t bHiB = sb + 33280 + (uint32_t)bsel * 32768;
        const uint32_t bLoB = bHiB + 16384;
        #pragma unroll
        for (int k16 = 0; k16 < 4; k16++) {
            const uint32_t colA = (uint32_t)(k16 * 32) + (((uint32_t)lane >> 4) << 4);
            const uint32_t colB = (uint32_t)(k16 * 32) + ((((uint32_t)lane >> 3) & 1) << 4);
            uint32_t afh[2][4], afl[2][4];
            #pragma unroll
            for (int mt = 0; mt < 2; mt++) {
                uint32_t row = (uint32_t)(wm * 32 + mt * 16 + (lane & 15) + tap);
                uint32_t ad = row * 128 + (colA ^ ((row & 7) << 4));
                LDSM_X4(afh[mt][0], afh[mt][1], afh[mt][2], afh[mt][3], aHiB + ad);
                LDSM_X4(afl[mt][0], afl[mt][1], afl[mt][2], afl[mt][3], aLoB + ad);
            }
            #pragma unroll
            for (int half = 0; half < 2; half++) {
                uint32_t bfh[4][2], bfl[4][2];
                #pragma unroll
                for (int np = 0; np < 2; np++) {
                    uint32_t row = (uint32_t)(wn * 64 + (half * 2 + np) * 16 +
                                              (((lane >> 4) << 3) | (lane & 7)));
                    uint32_t bd = row * 128 + (colB ^ ((row & 7) << 4));
                    LDSM_X4(bfh[2*np][0], bfh[2*np][1], bfh[2*np+1][0], bfh[2*np+1][1], bHiB + bd);
                    LDSM_X4(bfl[2*np][0], bfl[2*np][1], bfl[2*np+1][0], bfl[2*np+1][1], bLoB + bd);
                }
                #pragma unroll
                for (int mt = 0; mt < 2; mt++)
                    #pragma unroll
                    for (int nt = 0; nt < 4; nt++) {
                        float* ac = acc[mt][half * 4 + nt];
                        MMA16816(ac, afh[mt], bfh[nt]);
                        MMA16816(ac, afl[mt], bfh[nt]);
                        MMA16816(ac, afh[mt], bfl[nt]);
                    }
            }
        }

        if (lastTap && idx + 1 < NB) {
            __syncthreads();                 // all warps done reading A
            DO_COPY_A((idx + 1) / taps);
            CP_COMMIT();
        }
        CP_WAIT0();
        __syncthreads();
    }
    #undef DO_COPY_A
    #undef DO_COPY_B

    const int g  = lane >> 2;
    const int tg = lane & 3;
    if (gout == nullptr) {            // conv epilogue
        #pragma unroll
        for (int mt = 0; mt < 2; mt++) {
            const int mlo = m0 + wm * 32 + mt * 16 + g;
            const int mhi = mlo + 8;
            #pragma unroll
            for (int nt = 0; nt < 8; nt++) {
                const int n = n0 + wn * 64 + nt * 8 + tg * 2;
                const float al0 = g_alpha[layer][n],     be0 = g_beta[layer][n];
                const float al1 = g_alpha[layer][n + 1], be1 = g_beta[layer][n + 1];
                float v00 = fmaxf(fmaf(acc[mt][nt][0], al0, be0), 0.f);
                float v01 = fmaxf(fmaf(acc[mt][nt][1], al1, be1), 0.f);
                float v10 = fmaxf(fmaf(acc[mt][nt][2], al0, be0), 0.f);
                float v11 = fmaxf(fmaf(acc[mt][nt][3], al1, be1), 0.f);
                __nv_bfloat16 h00 = __float2bfloat16(v00), h01 = __float2bfloat16(v01);
                __nv_bfloat16 h10 = __float2bfloat16(v10), h11 = __float2bfloat16(v11);
                __nv_bfloat16 l00 = __float2bfloat16(v00 - __bfloat162float(h00));
                __nv_bfloat16 l01 = __float2bfloat16(v01 - __bfloat162float(h01));
                __nv_bfloat16 l10 = __float2bfloat16(v10 - __bfloat162float(h10));
                __nv_bfloat16 l11 = __float2bfloat16(v11 - __bfloat162float(h11));
                __nv_bfloat162 ph0; ph0.x = h00; ph0.y = h01;
                __nv_bfloat162 ph1; ph1.x = h10; ph1.y = h11;
                __nv_bfloat162 pl0; pl0.x = l00; pl0.y = l01;
                __nv_bfloat162 pl1; pl1.x = l10; pl1.y = l11;
                *(__nv_bfloat162*)(outHi + (size_t)mlo * DIM + n) = ph0;
                *(__nv_bfloat162*)(outHi + (size_t)mhi * DIM + n) = ph1;
                *(__nv_bfloat162*)(outLo + (size_t)mlo * DIM + n) = pl0;
                *(__nv_bfloat162*)(outLo + (size_t)mhi * DIM + n) = pl1;
            }
        }
    } else {                          // gates (bperm): smem transpose -> coalesced
        float* tile = (float*)smem;
        #pragma unroll
        for (int mt = 0; mt < 2; mt++) {
            const int rlo = wm * 32 + mt * 16 + g;
            const int rhi = rlo + 8;
            #pragma unroll
            for (int nt = 0; nt < 8; nt++) {
                const int nl = wn * 64 + nt * 8 + tg * 2;
                const float b0 = bias[n0 + nl], b1 = bias[n0 + nl + 1];
                tile[rlo * 129 + nl    ] = acc[mt][nt][0] + b0;
                tile[rlo * 129 + nl + 1] = acc[mt][nt][1] + b1;
                tile[rhi * 129 + nl    ] = acc[mt][nt][2] + b0;
                tile[rhi * 129 + nl + 1] = acc[mt][nt][3] + b1;
            }
        }
        __syncthreads();
        for (int i = tid; i < 16384; i += 256) {
            int b_  = i & 31;
            int nl  = (i >> 5) & 127;
            int tt  = i >> 12;
            gout[((size_t)(tb4 + tt) * GDIM + n0 + nl) * 32 + b_] =
                tile[(tt * 32 + b_) * 129 + nl];
        }
    }
}

// =================== persistent LSTM recurrence — 256 thr, cp.async staging ===
#define R_WHI 0
#define R_A   33280
#define R_PART 66560                        // 8*32*33*4 = 33792
#define R_OBH  100352                       // float[288] = 1152
#define R_OBP  101504                       // ushort[288] = 576
#define R_SMEM 102080

__global__ void __launch_bounds__(256, 1) lstm_recur_kernel(
    const __half* __restrict__ wrHi,
    const int* __restrict__ lengths, const float* __restrict__ gpreAll,
    float* __restrict__ out)
{
    extern __shared__ char sm[];
    float* part = (float*)(sm + R_PART);
    float* obh  = (float*)(sm + R_OBH);
    unsigned short* obp16 = (unsigned short*)(sm + R_OBP);
    __shared__ int len_s[32];

    const int tid = threadIdx.x;
    const int lane = tid & 31, u = tid >> 5;        // u in [0,8)
    const int dir = blockIdx.x >> 6;
    const int dc  = (blockIdx.x & 63) << 3;
    const uint32_t sb = smem_to_u32(sm);
    const float* gpre = gpreAll + (size_t)dir * MTOT * GDIM;
    const __half* wHi = wrHi + (size_t)dir * GDIM * DIM;
    unsigned* barP = &g_bar[dir][0];

    // stage W hi (permuted rows, 1040B padded stride)
    for (int i = tid; i < 2048; i += 256) {
        int r = i >> 6, c16 = i & 63;
        int n = ((r >> 3) << 9) + dc + (r & 7);
        uint4 vh = *(const uint4*)(wHi + (size_t)n * DIM + c16 * 8);
        *(uint4*)(sm + R_WHI + r * 1040 + c16 * 16) = vh;
    }
    if (tid < 32) len_s[tid] = lengths[tid];
    if (tid < 32)
        ((uint4*)g_h16[0][dir])[tid * 64 + (dc >> 3)] = make_uint4(0u, 0u, 0u, 0u);
    __syncthreads();

    // preload W fragments: 4 k16-tiles per warp (8 warps x 4 = 32 tiles = K512)
    uint32_t wf[4][8];
    {
        const uint32_t rB = (uint32_t)(((lane >> 4) << 3) | (lane & 7));
        const uint32_t hB = (uint32_t)(((lane >> 3) & 1) << 4);
        #pragma unroll
        for (int i = 0; i < 4; i++) {
            int kk = u * 4 + i;
            uint32_t col = (uint32_t)(kk * 32) + hB;
            LDSM_X4(wf[i][0], wf[i][1], wf[i][2], wf[i][3], sb + R_WHI + rB * 1040 + col);
            LDSM_X4(wf[i][4], wf[i][5], wf[i][6], wf[i][7], sb + R_WHI + (rB + 16) * 1040 + col);
        }
    }
    const int lenb = len_s[lane];

    // startup barrier (monotonic; counter freshly zeroed by bar_reset_kernel)
    __syncthreads();
    if (tid == 0) {
        unsigned prev = bar_arrive_(barP);
        if (prev != 63u) bar_wait_(barP, 64u);
    }
    __syncthreads();

    const uint32_t rA = (uint32_t)(lane & 15);
    const uint32_t hA = (uint32_t)((lane >> 4) << 4);
    float cst = 0.f;

    // gpre double-buffer: preload step 0 (thread = batch lane, dim dc+u)
    float gp0, gp1, gp2, gp3;
    {
        const int t0_ = dir ? (LSEQ - 1) : 0;
        const float* gq = gpre + ((size_t)t0_ * GDIM + dc + u) * 32 + lane;
        gp0 = __ldg(gq);
        gp1 = __ldg(gq + (size_t)512 * 32);
        gp2 = __ldg(gq + (size_t)1024 * 32);
        gp3 = __ldg(gq + (size_t)1536 * 32);
    }

    for (int s = 0; s < LSEQ; s++) {
        const int t = dir ? (LSEQ - 1 - s) : s;
        const int p = s & 1;
        const unsigned tgt = 64u * (unsigned)(s + 2);

        // stage h_prev fp16 via cp.async (zero-fill handles backward reset)
        {
            const __half* hp = g_h16[p][dir];
            #pragma unroll
            for (int i = 0; i < 8; i++) {
                int idx = i * 256 + tid;            // 0..2047
                int b_ = idx >> 6, c = idx & 63;
                int sz = (dir && t >= len_s[b_] - 1) ? 0 : 16;
                CP16Z(sb + R_A + (uint32_t)(b_ * 1040 + c * 16),
                      hp + ((size_t)idx << 3), sz);
            }
            CP_COMMIT();
        }

        // next-step gpre loads (issued while staging is in flight)
        float gn0 = 0.f, gn1 = 0.f, gn2 = 0.f, gn3 = 0.f;
        if (s + 1 < LSEQ) {
            const int tn = dir ? (LSEQ - 2 - s) : (s + 1);
            const float* gq = gpre + ((size_t)tn * GDIM + dc + u) * 32 + lane;
            gn0 = __ldg(gq);
            gn1 = __ldg(gq + (size_t)512 * 32);
            gn2 = __ldg(gq + (size_t)1024 * 32);
            gn3 = __ldg(gq + (size_t)1536 * 32);
        }

        CP_WAIT0();
        __syncthreads();                                 // (1)

        float acc[2][4][4];
        #pragma unroll
        for (int a = 0; a < 2; a++)
            #pragma unroll
            for (int b = 0; b < 4; b++)
                #pragma unroll
                for (int c = 0; c < 4; c++) acc[a][b][c] = 0.f;

        #pragma unroll
        for (int i = 0; i < 4; i++) {
            int kk = u * 4 + i;
            uint32_t col = (uint32_t)(kk * 32) + hA;
            uint32_t af0[4], af1[4];
            LDSM_X4(af0[0], af0[1], af0[2], af0[3], sb + R_A + rA * 1040 + col);
            LDSM_X4(af1[0], af1[1], af1[2], af1[3], sb + R_A + (rA + 16) * 1040 + col);
            #pragma unroll
            for (int nt = 0; nt < 4; nt++) {
                MMAF16(acc[0][nt], af0, &wf[i][nt * 2]);
                MMAF16(acc[1][nt], af1, &wf[i][nt * 2]);
            }
        }

        {
            int row = lane >> 2, colp = (lane & 3) * 2;
            #pragma unroll
            for (int mt = 0; mt < 2; mt++)
                #pragma unroll
                for (int nt = 0; nt < 4; nt++) {
                    float* p0 = part + (u * 32 + mt * 16 + row) * 33 + nt * 8 + colp;
                    p0[0] = acc[mt][nt][0]; p0[1] = acc[mt][nt][1];
                    float* p1 = part + (u * 32 + mt * 16 + row + 8) * 33 + nt * 8 + colp;
                    p1[0] = acc[mt][nt][2]; p1[1] = acc[mt][nt][3];
                }
        }
        __syncthreads();                                 // (2)

        // fused reduce + cell update: thread (b=lane, dim=dc+u), all 256 threads
        {
            float s0 = 0.f, s1 = 0.f, s2 = 0.f, s3 = 0.f;
            #pragma unroll
            for (int w = 0; w < 8; w++) {
                const float* pr = part + (w * 32 + lane) * 33;
                s0 += pr[u]; s1 += pr[8 + u]; s2 += pr[16 + u]; s3 += pr[24 + u];
            }
            float iv = sigmoid_fast_(gp0 + s0);
            float gv = tanh_fast_(gp1 + s1);
            float fv = sigmoid_fast_(gp2 + s2 + 1.f);
            float ov = sigmoid_fast_(gp3 + s3);
            if (dir && t >= lenb - 1) cst = 0.f;
            cst = fv * cst + iv * gv;
            float hh = ov * tanh_fast_(cst);
            obh[lane * 9 + u] = hh;
            obp16[lane * 9 + u] = __half_as_ushort(__float2half_rn(hh));
        }
        gp0 = gn0; gp1 = gn1; gp2 = gn2; gp3 = gn3;
        __syncthreads();                                 // (3)

        unsigned sdone = 0u;
        if (tid < 32) {   // publish h: one STG.128 per batch row
            const unsigned short* sp = obp16 + tid * 9;
            uint4 o4;
            o4.x = (unsigned)sp[0] | ((unsigned)sp[1] << 16);
            o4.y = (unsigned)sp[2] | ((unsigned)sp[3] << 16);
            o4.z = (unsigned)sp[4] | ((unsigned)sp[5] << 16);
            o4.w = (unsigned)sp[6] | ((unsigned)sp[7] << 16);
            ((uint4*)g_h16[p ^ 1][dir])[tid * 64 + (dc >> 3)] = o4;
            __syncwarp();
            if (tid == 0) {
                unsigned prev = bar_arrive_(barP);
                sdone = (prev == tgt - 1u) ? 1u : 0u;
            }
        }
        // out store off the critical path
        {
            int b2 = tid >> 3, d2 = tid & 7;
            out[(((size_t)b2 << 10) + t) * 1024 + (dir << 9) + dc + d2] = obh[b2 * 9 + d2];
        }
        if (tid == 0 && !sdone) bar_wait_(barP, tgt);
        __syncthreads();                                 // (4)
    }
}

// =================== launch ===================================================
extern "C" void kernel_launch(void* const* d_in, const int* in_sizes, int n_in,
                              void* d_out, int out_size)
{
    (void)in_sizes; (void)n_in; (void)out_size;
    const int*   x        = (const int*)  d_in[0];
    const int*   lengths  = (const int*)  d_in[1];
    const float* embed_w  = (const float*)d_in[2];
    const float* c1w = (const float*)d_in[3];
    const float* c1b = (const float*)d_in[4];
    const float* c2w = (const float*)d_in[5];
    const float* c2b = (const float*)d_in[6];
    const float* c3w = (const float*)d_in[7];
    const float* c3b = (const float*)d_in[8];
    const float* wf  = (const float*)d_in[9];
    const float* bf  = (const float*)d_in[10];
    const float* wb  = (const float*)d_in[11];
    const float* bb  = (const float*)d_in[12];
    const float* s1 = (const float*)d_in[13]; const float* o1 = (const float*)d_in[14];
    const float* m1 = (const float*)d_in[15]; const float* v1 = (const float*)d_in[16];
    const float* s2 = (const float*)d_in[17]; const float* o2 = (const float*)d_in[18];
    const float* m2 = (const float*)d_in[19]; const float* v2 = (const float*)d_in[20];
    const float* s3 = (const float*)d_in[21]; const float* o3 = (const float*)d_in[22];
    const float* m3 = (const float*)d_in[23]; const float* v3 = (const float*)d_in[24];
    float* out = (float*)d_out;

    __nv_bfloat16 *aHi, *aLo, *bHi, *bLo, *wcH, *wcL, *wgH, *wgL;
    __half *wrH;
    cudaGetSymbolAddress((void**)&aHi, g_aHi);
    cudaGetSymbolAddress((void**)&aLo, g_aLo);
    cudaGetSymbolAddress((void**)&bHi, g_bHi);
    cudaGetSymbolAddress((void**)&bLo, g_bLo);
    cudaGetSymbolAddress((void**)&wcH, g_wcHi);
    cudaGetSymbolAddress((void**)&wcL, g_wcLo);
    cudaGetSymbolAddress((void**)&wgH, g_wgHi);
    cudaGetSymbolAddress((void**)&wgL, g_wgLo);
    cudaGetSymbolAddress((void**)&wrH, g_wrHi);
    float* gpre;
    cudaGetSymbolAddress((void**)&gpre, g_gpre);

    const size_t WC = (size_t)3 * DIM * DIM;

    const int SMEM_GEMM  = 33280 + 2 * 32768;     // 98816
    cudaFuncSetAttribute(mma_gemm_kernel,
                         cudaFuncAttributeMaxDynamicSharedMemorySize, SMEM_GEMM);
    cudaFuncSetAttribute(lstm_recur_kernel,
                         cudaFuncAttributeMaxDynamicSharedMemorySize, R_SMEM);

    dim3 gconv(MTOT / 128, DIM / 128, 1);
    dim3 ggate(MTOT / 128, GDIM / 128, 2);
    dim3 bwp(32, 8);
    dim3 gwc(DIM / 32, DIM / 32, 9);
    dim3 gwg(DIM / 32, GDIM / 32, 2);

    bar_reset_kernel<<<1, 512>>>();               // determinism across replays
    wprep_conv_kernel<<<gwc, bwp>>>(c1w, c2w, c3w);
    bnprep_kernel<<<1, 512>>>(c1b, s1, o1, m1, v1,
                              c2b, s2, o2, m2, v2,
                              c3b, s3, o3, m3, v3);
    embed_kernel<<<MTOT, 128>>>(x, embed_w);
    mma_gemm_kernel<<<gconv, 256, SMEM_GEMM>>>(aHi, aLo, wcH + 0 * WC, wcL + 0 * WC,
        3, 0, 0, bHi, bLo, nullptr, nullptr, nullptr);
    mma_gemm_kernel<<<gconv, 256, SMEM_GEMM>>>(bHi, bLo, wcH + 1 * WC, wcL + 1 * WC,
        3, 1, 0, aHi, aLo, nullptr, nullptr, nullptr);
    mma_gemm_kernel<<<gconv, 256, SMEM_GEMM>>>(aHi, aLo, wcH + 2 * WC, wcL + 2 * WC,
        3, 2, 0, bHi, bLo, nullptr, nullptr, nullptr);
    wprep_gate_kernel<<<gwg, bwp>>>(wf, wb);
    wprep_rec_kernel<<<gwg, bwp>>>(wf, wb);
    mma_gemm_kernel<<<ggate, 256, SMEM_GEMM>>>(bHi, bLo, wgH, wgL,
        1, -1, 1, nullptr, nullptr, bf, bb, gpre);
    lstm_recur_kernel<<<128, 256, R_SMEM>>>(wrH, lengths, gpre, out);
}

// round 16
// speedup vs baseline: 1.0578x; 1.0578x over previous
#include <cuda_runtime.h>
#include <cuda_bf16.h>
#include <cuda_fp16.h>
#include <stdint.h>
#include <math.h>

#define BSZ   32
#define LSEQ  1024
#define DIM   512
#define MTOT  (BSZ*LSEQ)          // 32768
#define GDIM  2048                // 4*DIM

// =================== scratch (device globals) ================================
__device__ __align__(128) __nv_bfloat16 g_aHi[(size_t)MTOT*DIM];
__device__ __align__(128) __nv_bfloat16 g_aLo[(size_t)MTOT*DIM];
__device__ __align__(128) __nv_bfloat16 g_bHi[(size_t)MTOT*DIM];
__device__ __align__(128) __nv_bfloat16 g_bLo[(size_t)MTOT*DIM];
__device__ __align__(128) __nv_bfloat16 g_wcHi[3][(size_t)3*DIM*DIM];   // [layer][tap*512+n][k]
__device__ __align__(128) __nv_bfloat16 g_wcLo[3][(size_t)3*DIM*DIM];
__device__ __align__(128) __nv_bfloat16 g_wgHi[2][(size_t)GDIM*DIM];    // [dir][n][k]
__device__ __align__(128) __nv_bfloat16 g_wgLo[2][(size_t)GDIM*DIM];
__device__ __align__(128) __half g_wrHi[2][(size_t)GDIM*DIM];           // recurrent W fp16 (hi only)
__device__ float g_gpre[2][(size_t)MTOT*GDIM];   // [dir][ (t*2048 + col)*32 + b ]
__device__ __align__(128) __half g_h16[2][2][BSZ*DIM];  // [parity][dir][b*512+d]
__device__ float g_alpha[3][DIM];
__device__ float g_beta[3][DIM];
__device__ __align__(1024) unsigned g_bar[2][256];    // monotonic, dirs 1KB apart

// =================== primitives ===============================================
__device__ __forceinline__ uint32_t smem_to_u32(const void* p) {
    uint32_t a;
    asm("{ .reg .u64 t; cvta.to.shared.u64 t, %1; cvt.u32.u64 %0, t; }" : "=r"(a) : "l"(p));
    return a;
}
#define LDSM_X4(r0, r1, r2, r3, addr) \
    asm volatile("ldmatrix.sync.aligned.m8n8.x4.shared.b16 {%0,%1,%2,%3}, [%4];" \
        : "=r"(r0), "=r"(r1), "=r"(r2), "=r"(r3) : "r"(addr))
#define MMA16816(c, a, b) \
    asm volatile("mma.sync.aligned.m16n8k16.row.col.f32.bf16.bf16.f32 " \
        "{%0,%1,%2,%3}, {%4,%5,%6,%7}, {%8,%9}, {%0,%1,%2,%3};" \
        : "+f"((c)[0]), "+f"((c)[1]), "+f"((c)[2]), "+f"((c)[3]) \
        : "r"((a)[0]), "r"((a)[1]), "r"((a)[2]), "r"((a)[3]), \
          "r"((b)[0]), "r"((b)[1]))
#define MMAF16(c, a, b) \
    asm volatile("mma.sync.aligned.m16n8k16.row.col.f32.f16.f16.f32 " \
        "{%0,%1,%2,%3}, {%4,%5,%6,%7}, {%8,%9}, {%0,%1,%2,%3};" \
        : "+f"((c)[0]), "+f"((c)[1]), "+f"((c)[2]), "+f"((c)[3]) \
        : "r"((a)[0]), "r"((a)[1]), "r"((a)[2]), "r"((a)[3]), \
          "r"((b)[0]), "r"((b)[1]))

__device__ __forceinline__ float tanh_fast_(float x) {
    float y;
    asm("tanh.approx.f32 %0, %1;" : "=f"(y) : "f"(x));
    return y;
}
__device__ __forceinline__ float sigmoid_fast_(float x) {
    return fmaf(tanh_fast_(0.5f * x), 0.5f, 0.5f);
}
__device__ __forceinline__ unsigned bar_arrive_(unsigned* arr) {
    unsigned prev;
    asm volatile("atom.release.gpu.global.add.u32 %0, [%1], 1;"
                 : "=r"(prev) : "l"(arr) : "memory");
    return prev;
}
__device__ __forceinline__ void bar_wait_(unsigned* arr, unsigned tgt) {
    unsigned v;
    do {
        asm volatile("ld.acquire.gpu.global.u32 %0, [%1];" : "=r"(v) : "l"(arr));
    } while (v < tgt);
}

// =================== barrier reset (determinism across graph replays) ========
__global__ void bar_reset_kernel()
{
    g_bar[threadIdx.x >> 8][threadIdx.x & 255] = 0u;
}

// =================== BN fold =================================================
__global__ void bnprep_kernel(
    const float* __restrict__ b1, const float* __restrict__ s1, const float* __restrict__ o1,
    const float* __restrict__ m1, const float* __restrict__ v1,
    const float* __restrict__ b2, const float* __restrict__ s2, const float* __restrict__ o2,
    const float* __restrict__ m2, const float* __restrict__ v2,
    const float* __restrict__ b3, const float* __restrict__ s3, const float* __restrict__ o3,
    const float* __restrict__ m3, const float* __restrict__ v3)
{
    int i = threadIdx.x;
    if (i < DIM) {
        float g;
        g = s1[i] * rsqrtf(v1[i] + 1e-5f); g_alpha[0][i] = g; g_beta[0][i] = (b1[i] - m1[i]) * g + o1[i];
        g = s2[i] * rsqrtf(v2[i] + 1e-5f); g_alpha[1][i] = g; g_beta[1][i] = (b2[i] - m2[i]) * g + o2[i];
        g = s3[i] * rsqrtf(v3[i] + 1e-5f); g_alpha[2][i] = g; g_beta[2][i] = (b3[i] - m3[i]) * g + o3[i];
    }
}

// =================== weight prep (coalesced 32x32 transposes) =================
__global__ void wprep_conv_kernel(const float* __restrict__ c1,
                                  const float* __restrict__ c2,
                                  const float* __restrict__ c3)
{
    __shared__ float tile[32][33];
    const int tx = threadIdx.x, ty = threadIdx.y;
    const int k0 = blockIdx.x * 32, n0 = blockIdx.y * 32;
    const int layer = blockIdx.z / 3, tap = blockIdx.z % 3;
    const float* W = (layer == 0) ? c1 : ((layer == 1) ? c2 : c3);
    #pragma unroll
    for (int i = 0; i < 4; i++)
        tile[ty + i * 8][tx] = W[(size_t)(tap * DIM + k0 + ty + i * 8) * DIM + n0 + tx];
    __syncthreads();
    #pragma unroll
    for (int i = 0; i < 4; i++) {
        int n = n0 + ty + i * 8;
        float v = tile[tx][ty + i * 8];
        __nv_bfloat16 h = __float2bfloat16(v);
        __nv_bfloat16 l = __float2bfloat16(v - __bfloat162float(h));
        g_wcHi[layer][(size_t)(tap * DIM + n) * DIM + k0 + tx] = h;
        g_wcLo[layer][(size_t)(tap * DIM + n) * DIM + k0 + tx] = l;
    }
}
// merged LSTM weight prep: z in [0,4): dir = z&1, rec = z>>1.
// rec=0: input rows k<512 -> bf16 hi/lo gate weights.
// rec=1: rows 512..1023 -> fp16 recurrent weights (hi only).
__global__ void wprep_lstm_kernel(const float* __restrict__ Wf,
                                  const float* __restrict__ Wb)
{
    __shared__ float tile[32][33];
    const int tx = threadIdx.x, ty = threadIdx.y;
    const int k0 = blockIdx.x * 32, n0 = blockIdx.y * 32;
    const int dir = blockIdx.z & 1, rec = blockIdx.z >> 1;
    const float* W = dir ? Wb : Wf;
    const int krow0 = rec ? DIM : 0;
    #pragma unroll
    for (int i = 0; i < 4; i++)
        tile[ty + i * 8][tx] = W[(size_t)(krow0 + k0 + ty + i * 8) * GDIM + n0 + tx];
    __syncthreads();
    #pragma unroll
    for (int i = 0; i < 4; i++) {
        int n = n0 + ty + i * 8;
        float v = tile[tx][ty + i * 8];
        if (rec) {
            g_wrHi[dir][(size_t)n * DIM + k0 + tx] = __float2half_rn(v);
        } else {
            __nv_bfloat16 h = __float2bfloat16(v);
            __nv_bfloat16 l = __float2bfloat16(v - __bfloat162float(h));
            g_wgHi[dir][(size_t)n * DIM + k0 + tx] = h;
            g_wgLo[dir][(size_t)n * DIM + k0 + tx] = l;
        }
    }
}

// =================== embedding -> bf16 hi/lo =================================
__global__ void embed_kernel(const int* __restrict__ x, const float* __restrict__ ew)
{
    int m = blockIdx.x;
    int tok = x[m];
    int j = threadIdx.x;
    float4 v = ((const float4*)(ew + (size_t)tok * DIM))[j];
    float f[4] = {v.x, v.y, v.z, v.w};
    __nv_bfloat16 h[4], l[4];
    #pragma unroll
    for (int i = 0; i < 4; i++) {
        h[i] = __float2bfloat16(f[i]);
        l[i] = __float2bfloat16(f[i] - __bfloat162float(h[i]));
    }
    *(uint2*)(g_aHi + (size_t)m * DIM + j * 4) = *(uint2*)h;
    *(uint2*)(g_aLo + (size_t)m * DIM + j * 4) = *(uint2*)l;
}

// =================== bf16 mma.sync GEMM (R14 proven engine) ===================
__global__ void __launch_bounds__(256, 2) mma_gemm_kernel(
    const __nv_bfloat16* __restrict__ Ahi, const __nv_bfloat16* __restrict__ Alo,
    const __nv_bfloat16* __restrict__ BwHi, const __nv_bfloat16* __restrict__ BwLo,
    int taps, int layer, int bperm,
    __nv_bfloat16* __restrict__ outHi, __nv_bfloat16* __restrict__ outLo,
    const float* __restrict__ biasA, const float* __restrict__ biasB,
    float* __restrict__ gout)
{
    extern __shared__ char smem[];
    const int tid = threadIdx.x;
    const int lane = tid & 31, wid = tid >> 5;
    const int wm = wid & 3, wn = wid >> 2;
    const int m0 = blockIdx.x * 128, n0 = blockIdx.y * 128;
    const int t0 = m0 & (LSEQ - 1);
    const int tb4 = blockIdx.x * 4;
    const int dz = blockIdx.z;
    const uint32_t sb = smem_to_u32(smem);

    if (bperm) {
        BwHi += (size_t)dz * GDIM * DIM;
        BwLo += (size_t)dz * GDIM * DIM;
        gout += (size_t)dz * MTOT * GDIM;
    }
    const float* bias = dz ? biasB : biasA;

    const int off0  = taps >> 1;
    const int arows = 128 + (taps - 1);

    float acc[2][8][4];
    #pragma unroll
    for (int a = 0; a < 2; a++)
        #pragma unroll
        for (int b = 0; b < 8; b++)
            #pragma unroll
            for (int c = 0; c < 4; c++) acc[a][b][c] = 0.f;

    #define DO_COPY_A(SLICE) do { \
        const int _kb = (SLICE) << 6; \
        const int _tot = arows * 8; \
        for (int _i = tid; _i < _tot; _i += 256) { \
            int _r = _i >> 3, _c8 = (_i & 7) << 3; \
            uint32_t _off = (uint32_t)(_r * 128) + (((uint32_t)_c8 * 2) ^ (((uint32_t)_r & 7) << 4)); \
            uint4 _vh = make_uint4(0u,0u,0u,0u), _vl = _vh; \
            if (bperm) { \
                size_t _ga = (size_t)(((_r & 31) << 10) + tb4 + (_r >> 5)) * DIM + _kb + _c8; \
                _vh = *(const uint4*)(Ahi + _ga); \
                _vl = *(const uint4*)(Alo + _ga); \
            } else { \
                int _tl = t0 + _r - off0; \
                if (_tl >= 0 && _tl < LSEQ) { \
                    size_t _ga = (size_t)(m0 + _r - off0) * DIM + _kb + _c8; \
                    _vh = *(const uint4*)(Ahi + _ga); \
                    _vl = *(const uint4*)(Alo + _ga); \
                } \
            } \
            *(uint4*)(smem + _off) = _vh; \
            *(uint4*)(smem + 16640 + _off) = _vl; \
        } \
    } while (0)

    #define DO_COPY_B(IDX, ST) do { \
        const int _sl = (IDX) / taps, _tp = (IDX) % taps; \
        const int _kb = _sl << 6; \
        const int _rbase = (taps == 3 ? _tp * DIM : 0) + n0; \
        char* _bp = smem + 33280 + (ST) * 32768; \
        for (int _i = tid; _i < 1024; _i += 256) { \
            int _r = _i >> 3, _c8 = (_i & 7) << 3; \
            uint32_t _off = (uint32_t)(_r * 128) + (((uint32_t)_c8 * 2) ^ (((uint32_t)_r & 7) << 4)); \
            size_t _ga = (size_t)(_rbase + _r) * DIM + _kb + _c8; \
            *(uint4*)(_bp + _off) = *(const uint4*)(BwHi + _ga); \
            *(uint4*)(_bp + 16384 + _off) = *(const uint4*)(BwLo + _ga); \
        } \
    } while (0)

    const int NB = 8 * taps;
    DO_COPY_A(0);
    DO_COPY_B(0, 0);
    __syncthreads();

    for (int idx = 0; idx < NB; idx++) {
        const int tap = idx % taps;
        const int bsel = idx & 1;
        const bool lastTap = (tap == taps - 1);

        if (idx + 1 < NB) DO_COPY_B(idx + 1, bsel ^ 1);

        const uint32_t aHiB = sb;
        const uint32_t aLoB = sb + 16640;
        const uint32_t bHiB = sb + 33280 + (uint32_t)bsel * 32768;
        const uint32_t bLoB = bHiB + 16384;
        #pragma unroll
        for (int k16 = 0; k16 < 4; k16++) {
            const uint32_t colA = (uint32_t)(k16 * 32) + (((uint32_t)lane >> 4) << 4);
            const uint32_t colB = (uint32_t)(k16 * 32) + ((((uint32_t)lane >> 3) & 1) << 4);
            uint32_t afh[2][4], afl[2][4];
            #pragma unroll
            for (int mt = 0; mt < 2; mt++) {
                uint32_t row = (uint32_t)(wm * 32 + mt * 16 + (lane & 15) + tap);
                uint32_t ad = row * 128 + (colA ^ ((row & 7) << 4));
                LDSM_X4(afh[mt][0], afh[mt][1], afh[mt][2], afh[mt][3], aHiB + ad);
                LDSM_X4(afl[mt][0], afl[mt][1], afl[mt][2], afl[mt][3], aLoB + ad);
            }
            #pragma unroll
            for (int half = 0; half < 2; half++) {
                uint32_t bfh[4][2], bfl[4][2];
                #pragma unroll
                for (int np = 0; np < 2; np++) {
                    uint32_t row = (uint32_t)(wn * 64 + (half * 2 + np) * 16 +
                                              (((lane >> 4) << 3) | (lane & 7)));
                    uint32_t bd = row * 128 + (colB ^ ((row & 7) << 4));
                    LDSM_X4(bfh[2*np][0], bfh[2*np][1], bfh[2*np+1][0], bfh[2*np+1][1], bHiB + bd);
                    LDSM_X4(bfl[2*np][0], bfl[2*np][1], bfl[2*np+1][0], bfl[2*np+1][1], bLoB + bd);
                }
                #pragma unroll
                for (int mt = 0; mt < 2; mt++)
                    #pragma unroll
                    for (int nt = 0; nt < 4; nt++) {
                        float* ac = acc[mt][half * 4 + nt];
                        MMA16816(ac, afh[mt], bfh[nt]);
                        MMA16816(ac, afl[mt], bfh[nt]);
                        MMA16816(ac, afh[mt], bfl[nt]);
                    }
            }
        }
        __syncthreads();
        if (lastTap && idx + 1 < NB) {
            DO_COPY_A((idx + 1) / taps);
            __syncthreads();
        }
    }
    #undef DO_COPY_A
    #undef DO_COPY_B

    const int g  = lane >> 2;
    const int tg = lane & 3;
    if (gout == nullptr) {            // conv epilogue
        #pragma unroll
        for (int mt = 0; mt < 2; mt++) {
            const int mlo = m0 + wm * 32 + mt * 16 + g;
            const int mhi = mlo + 8;
            #pragma unroll
            for (int nt = 0; nt < 8; nt++) {
                const int n = n0 + wn * 64 + nt * 8 + tg * 2;
                const float al0 = g_alpha[layer][n],     be0 = g_beta[layer][n];
                const float al1 = g_alpha[layer][n + 1], be1 = g_beta[layer][n + 1];
                float v00 = fmaxf(fmaf(acc[mt][nt][0], al0, be0), 0.f);
                float v01 = fmaxf(fmaf(acc[mt][nt][1], al1, be1), 0.f);
                float v10 = fmaxf(fmaf(acc[mt][nt][2], al0, be0), 0.f);
                float v11 = fmaxf(fmaf(acc[mt][nt][3], al1, be1), 0.f);
                __nv_bfloat16 h00 = __float2bfloat16(v00), h01 = __float2bfloat16(v01);
                __nv_bfloat16 h10 = __float2bfloat16(v10), h11 = __float2bfloat16(v11);
                __nv_bfloat16 l00 = __float2bfloat16(v00 - __bfloat162float(h00));
                __nv_bfloat16 l01 = __float2bfloat16(v01 - __bfloat162float(h01));
                __nv_bfloat16 l10 = __float2bfloat16(v10 - __bfloat162float(h10));
                __nv_bfloat16 l11 = __float2bfloat16(v11 - __bfloat162float(h11));
                __nv_bfloat162 ph0; ph0.x = h00; ph0.y = h01;
                __nv_bfloat162 ph1; ph1.x = h10; ph1.y = h11;
                __nv_bfloat162 pl0; pl0.x = l00; pl0.y = l01;
                __nv_bfloat162 pl1; pl1.x = l10; pl1.y = l11;
                *(__nv_bfloat162*)(outHi + (size_t)mlo * DIM + n) = ph0;
                *(__nv_bfloat162*)(outHi + (size_t)mhi * DIM + n) = ph1;
                *(__nv_bfloat162*)(outLo + (size_t)mlo * DIM + n) = pl0;
                *(__nv_bfloat162*)(outLo + (size_t)mhi * DIM + n) = pl1;
            }
        }
    } else {                          // gates (bperm): smem transpose -> coalesced
        float* tile = (float*)smem;
        #pragma unroll
        for (int mt = 0; mt < 2; mt++) {
            const int rlo = wm * 32 + mt * 16 + g;
            const int rhi = rlo + 8;
            #pragma unroll
            for (int nt = 0; nt < 8; nt++) {
                const int nl = wn * 64 + nt * 8 + tg * 2;
                const float b0 = bias[n0 + nl], b1 = bias[n0 + nl + 1];
                tile[rlo * 129 + nl    ] = acc[mt][nt][0] + b0;
                tile[rlo * 129 + nl + 1] = acc[mt][nt][1] + b1;
                tile[rhi * 129 + nl    ] = acc[mt][nt][2] + b0;
                tile[rhi * 129 + nl + 1] = acc[mt][nt][3] + b1;
            }
        }
        __syncthreads();
        for (int i = tid; i < 16384; i += 256) {
            int b_  = i & 31;
            int nl  = (i >> 5) & 127;
            int tt  = i >> 12;
            gout[((size_t)(tb4 + tt) * GDIM + n0 + nl) * 32 + b_] =
                tile[(tt * 32 + b_) * 129 + nl];
        }
    }
}

// =================== persistent LSTM recurrence (R14 proven) ==================
#define R_WHI 0
#define R_A   33280
#define R_PART 66560                        // 8*32*33*4 = 33792
#define R_OBH  100352                       // float[288] = 1152
#define R_OBP  101504                       // ushort[288] = 576
#define R_SMEM 102080

__global__ void __launch_bounds__(256, 1) lstm_recur_kernel(
    const __half* __restrict__ wrHi,
    const int* __restrict__ lengths, const float* __restrict__ gpreAll,
    float* __restrict__ out)
{
    extern __shared__ char sm[];
    float* part = (float*)(sm + R_PART);
    float* obh  = (float*)(sm + R_OBH);
    unsigned short* obp16 = (unsigned short*)(sm + R_OBP);
    __shared__ int len_s[32];

    const int tid = threadIdx.x;
    const int lane = tid & 31, u = tid >> 5;        // u in [0,8)
    const int dir = blockIdx.x >> 6;
    const int dc  = (blockIdx.x & 63) << 3;
    const uint32_t sb = smem_to_u32(sm);
    const float* gpre = gpreAll + (size_t)dir * MTOT * GDIM;
    const __half* wHi = wrHi + (size_t)dir * GDIM * DIM;
    unsigned* barP = &g_bar[dir][0];

    // stage W hi (permuted rows, 1040B padded stride)
    for (int i = tid; i < 2048; i += 256) {
        int r = i >> 6, c16 = i & 63;
        int n = ((r >> 3) << 9) + dc + (r & 7);
        uint4 vh = *(const uint4*)(wHi + (size_t)n * DIM + c16 * 8);
        *(uint4*)(sm + R_WHI + r * 1040 + c16 * 16) = vh;
    }
    if (tid < 32) len_s[tid] = lengths[tid];
    if (tid < 32)
        ((uint4*)g_h16[0][dir])[tid * 64 + (dc >> 3)] = make_uint4(0u, 0u, 0u, 0u);
    __syncthreads();

    // preload W fragments: 4 k16-tiles per warp (8 warps x 4 = 32 tiles = K512)
    uint32_t wf[4][8];
    {
        const uint32_t rB = (uint32_t)(((lane >> 4) << 3) | (lane & 7));
        const uint32_t hB = (uint32_t)(((lane >> 3) & 1) << 4);
        #pragma unroll
        for (int i = 0; i < 4; i++) {
            int kk = u * 4 + i;
            uint32_t col = (uint32_t)(kk * 32) + hB;
            LDSM_X4(wf[i][0], wf[i][1], wf[i][2], wf[i][3], sb + R_WHI + rB * 1040 + col);
            LDSM_X4(wf[i][4], wf[i][5], wf[i][6], wf[i][7], sb + R_WHI + (rB + 16) * 1040 + col);
        }
    }
    const int lenb = len_s[lane];

    // startup barrier (monotonic; counter freshly zeroed by bar_reset_kernel)
    __syncthreads();
    if (tid == 0) {
        unsigned prev = bar_arrive_(barP);
        if (prev != 63u) bar_wait_(barP, 64u);
    }
    __syncthreads();

    const uint32_t rA = (uint32_t)(lane & 15);
    const uint32_t hA = (uint32_t)((lane >> 4) << 4);
    float cst = 0.f;

    // gpre double-buffer: preload step 0 (thread = batch lane, dim dc+u)
    float gp0, gp1, gp2, gp3;
    {
        const int t0_ = dir ? (LSEQ - 1) : 0;
        const float* gq = gpre + ((size_t)t0_ * GDIM + dc + u) * 32 + lane;
        gp0 = __ldg(gq);
        gp1 = __ldg(gq + (size_t)512 * 32);
        gp2 = __ldg(gq + (size_t)1024 * 32);
        gp3 = __ldg(gq + (size_t)1536 * 32);
    }

    for (int s = 0; s < LSEQ; s++) {
        const int t = dir ? (LSEQ - 1 - s) : s;
        const int p = s & 1;
        const unsigned tgt = 64u * (unsigned)(s + 2);

        // next-step gpre loads (hidden behind this step)
        float gn0 = 0.f, gn1 = 0.f, gn2 = 0.f, gn3 = 0.f;
        if (s + 1 < LSEQ) {
            const int tn = dir ? (LSEQ - 2 - s) : (s + 1);
            const float* gq = gpre + ((size_t)tn * GDIM + dc + u) * 32 + lane;
            gn0 = __ldg(gq);
            gn1 = __ldg(gq + (size_t)512 * 32);
            gn2 = __ldg(gq + (size_t)1024 * 32);
            gn3 = __ldg(gq + (size_t)1536 * 32);
        }

        {   // stage h_prev fp16: 32KB, 8 uint4/thread (register-staged LDG->STS)
            const uint4* hp = (const uint4*)g_h16[p][dir];
            #pragma unroll
            for (int i = 0; i < 8; i++) {
                int idx = i * 256 + tid;            // 0..2047
                int b_ = idx >> 6, c = idx & 63;
                uint4 v = __ldcg(hp + idx);
                if (dir && t >= len_s[b_] - 1) v = make_uint4(0u, 0u, 0u, 0u);
                *(uint4*)(sm + R_A + b_ * 1040 + c * 16) = v;
            }
        }
        __syncthreads();                                 // (1)

        float acc[2][4][4];
        #pragma unroll
        for (int a = 0; a < 2; a++)
            #pragma unroll
            for (int b = 0; b < 4; b++)
                #pragma unroll
                for (int c = 0; c < 4; c++) acc[a][b][c] = 0.f;

        #pragma unroll
        for (int i = 0; i < 4; i++) {
            int kk = u * 4 + i;
            uint32_t col = (uint32_t)(kk * 32) + hA;
            uint32_t af0[4], af1[4];
            LDSM_X4(af0[0], af0[1], af0[2], af0[3], sb + R_A + rA * 1040 + col);
            LDSM_X4(af1[0], af1[1], af1[2], af1[3], sb + R_A + (rA + 16) * 1040 + col);
            #pragma unroll
            for (int nt = 0; nt < 4; nt++) {
                MMAF16(acc[0][nt], af0, &wf[i][nt * 2]);
                MMAF16(acc[1][nt], af1, &wf[i][nt * 2]);
            }
        }

        {
            int row = lane >> 2, colp = (lane & 3) * 2;
            #pragma unroll
            for (int mt = 0; mt < 2; mt++)
                #pragma unroll
                for (int nt = 0; nt < 4; nt++) {
                    float* p0 = part + (u * 32 + mt * 16 + row) * 33 + nt * 8 + colp;
                    p0[0] = acc[mt][nt][0]; p0[1] = acc[mt][nt][1];
                    float* p1 = part + (u * 32 + mt * 16 + row + 8) * 33 + nt * 8 + colp;
                    p1[0] = acc[mt][nt][2]; p1[1] = acc[mt][nt][3];
                }
        }
        __syncthreads();                                 // (2)

        // fused reduce + cell update: thread (b=lane, dim=dc+u), all 256 threads
        {
            float s0 = 0.f, s1 = 0.f, s2 = 0.f, s3 = 0.f;
            #pragma unroll
            for (int w = 0; w < 8; w++) {
                const float* pr = part + (w * 32 + lane) * 33;
                s0 += pr[u]; s1 += pr[8 + u]; s2 += pr[16 + u]; s3 += pr[24 + u];
            }
            float iv = sigmoid_fast_(gp0 + s0);
            float gv = tanh_fast_(gp1 + s1);
            float fv = sigmoid_fast_(gp2 + s2 + 1.f);
            float ov = sigmoid_fast_(gp3 + s3);
            if (dir && t >= lenb - 1) cst = 0.f;
            cst = fv * cst + iv * gv;
            float hh = ov * tanh_fast_(cst);
            obh[lane * 9 + u] = hh;
            obp16[lane * 9 + u] = __half_as_ushort(__float2half_rn(hh));
        }
        gp0 = gn0; gp1 = gn1; gp2 = gn2; gp3 = gn3;
        __syncthreads();                                 // (3)

        unsigned sdone = 0u;
        if (tid < 32) {   // publish h: one STG.128 per batch row
            const unsigned short* sp = obp16 + tid * 9;
            uint4 o4;
            o4.x = (unsigned)sp[0] | ((unsigned)sp[1] << 16);
            o4.y = (unsigned)sp[2] | ((unsigned)sp[3] << 16);
            o4.z = (unsigned)sp[4] | ((unsigned)sp[5] << 16);
            o4.w = (unsigned)sp[6] | ((unsigned)sp[7] << 16);
            ((uint4*)g_h16[p ^ 1][dir])[tid * 64 + (dc >> 3)] = o4;
            __syncwarp();
            if (tid == 0) {
                unsigned prev = bar_arrive_(barP);
                sdone = (prev == tgt - 1u) ? 1u : 0u;
            }
        }
        // out store off the critical path
        {
            int b2 = tid >> 3, d2 = tid & 7;
            out[(((size_t)b2 << 10) + t) * 1024 + (dir << 9) + dc + d2] = obh[b2 * 9 + d2];
        }
        if (tid == 0 && !sdone) bar_wait_(barP, tgt);
        __syncthreads();                                 // (4)
    }
}

// =================== launch ===================================================
extern "C" void kernel_launch(void* const* d_in, const int* in_sizes, int n_in,
                              void* d_out, int out_size)
{
    (void)in_sizes; (void)n_in; (void)out_size;
    const int*   x        = (const int*)  d_in[0];
    const int*   lengths  = (const int*)  d_in[1];
    const float* embed_w  = (const float*)d_in[2];
    const float* c1w = (const float*)d_in[3];
    const float* c1b = (const float*)d_in[4];
    const float* c2w = (const float*)d_in[5];
    const float* c2b = (const float*)d_in[6];
    const float* c3w = (const float*)d_in[7];
    const float* c3b = (const float*)d_in[8];
    const float* wf  = (const float*)d_in[9];
    const float* bf  = (const float*)d_in[10];
    const float* wb  = (const float*)d_in[11];
    const float* bb  = (const float*)d_in[12];
    const float* s1 = (const float*)d_in[13]; const float* o1 = (const float*)d_in[14];
    const float* m1 = (const float*)d_in[15]; const float* v1 = (const float*)d_in[16];
    const float* s2 = (const float*)d_in[17]; const float* o2 = (const float*)d_in[18];
    const float* m2 = (const float*)d_in[19]; const float* v2 = (const float*)d_in[20];
    const float* s3 = (const float*)d_in[21]; const float* o3 = (const float*)d_in[22];
    const float* m3 = (const float*)d_in[23]; const float* v3 = (const float*)d_in[24];
    float* out = (float*)d_out;

    __nv_bfloat16 *aHi, *aLo, *bHi, *bLo, *wcH, *wcL, *wgH, *wgL;
    __half *wrH;
    cudaGetSymbolAddress((void**)&aHi, g_aHi);
    cudaGetSymbolAddress((void**)&aLo, g_aLo);
    cudaGetSymbolAddress((void**)&bHi, g_bHi);
    cudaGetSymbolAddress((void**)&bLo, g_bLo);
    cudaGetSymbolAddress((void**)&wcH, g_wcHi);
    cudaGetSymbolAddress((void**)&wcL, g_wcLo);
    cudaGetSymbolAddress((void**)&wgH, g_wgHi);
    cudaGetSymbolAddress((void**)&wgL, g_wgLo);
    cudaGetSymbolAddress((void**)&wrH, g_wrHi);
    float* gpre;
    cudaGetSymbolAddress((void**)&gpre, g_gpre);

    const size_t WC = (size_t)3 * DIM * DIM;

    const int SMEM_GEMM  = 33280 + 2 * 32768;     // 98816
    cudaFuncSetAttribute(mma_gemm_kernel,
                         cudaFuncAttributeMaxDynamicSharedMemorySize, SMEM_GEMM);
    cudaFuncSetAttribute(lstm_recur_kernel,
                         cudaFuncAttributeMaxDynamicSharedMemorySize, R_SMEM);

    dim3 gconv(MTOT / 128, DIM / 128, 1);
    dim3 ggate(MTOT / 128, GDIM / 128, 2);
    dim3 bwp(32, 8);
    dim3 gwc(DIM / 32, DIM / 32, 9);
    dim3 gwl(DIM / 32, GDIM / 32, 4);   // merged gate+rec prep: dir | rec<<1

    bar_reset_kernel<<<1, 512>>>();               // determinism across replays
    wprep_conv_kernel<<<gwc, bwp>>>(c1w, c2w, c3w);
    bnprep_kernel<<<1, 512>>>(c1b, s1, o1, m1, v1,
                              c2b, s2, o2, m2, v2,
                              c3b, s3, o3, m3, v3);
    embed_kernel<<<MTOT, 128>>>(x, embed_w);
    mma_gemm_kernel<<<gconv, 256, SMEM_GEMM>>>(aHi, aLo, wcH + 0 * WC, wcL + 0 * WC,
        3, 0, 0, bHi, bLo, nullptr, nullptr, nullptr);
    mma_gemm_kernel<<<gconv, 256, SMEM_GEMM>>>(bHi, bLo, wcH + 1 * WC, wcL + 1 * WC,
        3, 1, 0, aHi, aLo, nullptr, nullptr, nullptr);
    mma_gemm_kernel<<<gconv, 256, SMEM_GEMM>>>(aHi, aLo, wcH + 2 * WC, wcL + 2 * WC,
        3, 2, 0, bHi, bLo, nullptr, nullptr, nullptr);
    wprep_lstm_kernel<<<gwl, bwp>>>(wf, wb);
    mma_gemm_kernel<<<ggate, 256, SMEM_GEMM>>>(bHi, bLo, wgH, wgL,
        1, -1, 1, nullptr, nullptr, bf, bb, gpre);
    lstm_recur_kernel<<<128, 256, R_SMEM>>>(wrH, lengths, gpre, out);
}

// round 17
// speedup vs baseline: 1.1771x; 1.1128x over previous
#include <cuda_runtime.h>
#include <cuda_bf16.h>
#include <cuda_fp16.h>
#include <stdint.h>
#include <math.h>

#define BSZ   32
#define LSEQ  1024
#define DIM   512
#define MTOT  (BSZ*LSEQ)          // 32768
#define GDIM  2048                // 4*DIM

// =================== scratch (device globals) ================================
__device__ __align__(128) __nv_bfloat16 g_aHi[(size_t)MTOT*DIM];
__device__ __align__(128) __nv_bfloat16 g_aLo[(size_t)MTOT*DIM];
__device__ __align__(128) __nv_bfloat16 g_bHi[(size_t)MTOT*DIM];   // conv3 out: fp16 (reinterp)
__device__ __align__(128) __nv_bfloat16 g_bLo[(size_t)MTOT*DIM];
__device__ __align__(128) __nv_bfloat16 g_wcHi[3][(size_t)3*DIM*DIM];   // [layer][tap*512+n][k]
__device__ __align__(128) __nv_bfloat16 g_wcLo[3][(size_t)3*DIM*DIM];
__device__ __align__(128) __half g_wgF16[2][(size_t)GDIM*DIM];          // gate W fp16 [dir][n][k]
__device__ __align__(128) __half g_wrHi[2][(size_t)GDIM*DIM];           // recurrent W fp16
__device__ float g_gpre[2][(size_t)MTOT*GDIM];   // [dir][ (t*2048 + col)*32 + b ]
__device__ __align__(128) __half g_h16[2][2][BSZ*DIM];  // [parity][dir][b*512+d]
__device__ float g_alpha[3][DIM];
__device__ float g_beta[3][DIM];
__device__ __align__(1024) unsigned g_bar[2][256];    // monotonic, dirs 1KB apart

// =================== primitives ===============================================
__device__ __forceinline__ uint32_t smem_to_u32(const void* p) {
    uint32_t a;
    asm("{ .reg .u64 t; cvta.to.shared.u64 t, %1; cvt.u32.u64 %0, t; }" : "=r"(a) : "l"(p));
    return a;
}
#define LDSM_X4(r0, r1, r2, r3, addr) \
    asm volatile("ldmatrix.sync.aligned.m8n8.x4.shared.b16 {%0,%1,%2,%3}, [%4];" \
        : "=r"(r0), "=r"(r1), "=r"(r2), "=r"(r3) : "r"(addr))
#define MMA16816(c, a, b) \
    asm volatile("mma.sync.aligned.m16n8k16.row.col.f32.bf16.bf16.f32 " \
        "{%0,%1,%2,%3}, {%4,%5,%6,%7}, {%8,%9}, {%0,%1,%2,%3};" \
        : "+f"((c)[0]), "+f"((c)[1]), "+f"((c)[2]), "+f"((c)[3]) \
        : "r"((a)[0]), "r"((a)[1]), "r"((a)[2]), "r"((a)[3]), \
          "r"((b)[0]), "r"((b)[1]))
#define MMAF16(c, a, b) \
    asm volatile("mma.sync.aligned.m16n8k16.row.col.f32.f16.f16.f32 " \
        "{%0,%1,%2,%3}, {%4,%5,%6,%7}, {%8,%9}, {%0,%1,%2,%3};" \
        : "+f"((c)[0]), "+f"((c)[1]), "+f"((c)[2]), "+f"((c)[3]) \
        : "r"((a)[0]), "r"((a)[1]), "r"((a)[2]), "r"((a)[3]), \
          "r"((b)[0]), "r"((b)[1]))

__device__ __forceinline__ float tanh_fast_(float x) {
    float y;
    asm("tanh.approx.f32 %0, %1;" : "=f"(y) : "f"(x));
    return y;
}
__device__ __forceinline__ float sigmoid_fast_(float x) {
    return fmaf(tanh_fast_(0.5f * x), 0.5f, 0.5f);
}
__device__ __forceinline__ unsigned bar_arrive_(unsigned* arr) {
    unsigned prev;
    asm volatile("atom.release.gpu.global.add.u32 %0, [%1], 1;"
                 : "=r"(prev) : "l"(arr) : "memory");
    return prev;
}
__device__ __forceinline__ void bar_wait_(unsigned* arr, unsigned tgt) {
    unsigned v;
    do {
        asm volatile("ld.acquire.gpu.global.u32 %0, [%1];" : "=r"(v) : "l"(arr));
    } while (v < tgt);
}

// =================== barrier reset (determinism across graph replays) ========
__global__ void bar_reset_kernel()
{
    g_bar[threadIdx.x >> 8][threadIdx.x & 255] = 0u;
}

// =================== BN fold =================================================
__global__ void bnprep_kernel(
    const float* __restrict__ b1, const float* __restrict__ s1, const float* __restrict__ o1,
    const float* __restrict__ m1, const float* __restrict__ v1,
    const float* __restrict__ b2, const float* __restrict__ s2, const float* __restrict__ o2,
    const float* __restrict__ m2, const float* __restrict__ v2,
    const float* __restrict__ b3, const float* __restrict__ s3, const float* __restrict__ o3,
    const float* __restrict__ m3, const float* __restrict__ v3)
{
    int i = threadIdx.x;
    if (i < DIM) {
        float g;
        g = s1[i] * rsqrtf(v1[i] + 1e-5f); g_alpha[0][i] = g; g_beta[0][i] = (b1[i] - m1[i]) * g + o1[i];
        g = s2[i] * rsqrtf(v2[i] + 1e-5f); g_alpha[1][i] = g; g_beta[1][i] = (b2[i] - m2[i]) * g + o2[i];
        g = s3[i] * rsqrtf(v3[i] + 1e-5f); g_alpha[2][i] = g; g_beta[2][i] = (b3[i] - m3[i]) * g + o3[i];
    }
}

// =================== weight prep (coalesced 32x32 transposes) =================
__global__ void wprep_conv_kernel(const float* __restrict__ c1,
                                  const float* __restrict__ c2,
                                  const float* __restrict__ c3)
{
    __shared__ float tile[32][33];
    const int tx = threadIdx.x, ty = threadIdx.y;
    const int k0 = blockIdx.x * 32, n0 = blockIdx.y * 32;
    const int layer = blockIdx.z / 3, tap = blockIdx.z % 3;
    const float* W = (layer == 0) ? c1 : ((layer == 1) ? c2 : c3);
    #pragma unroll
    for (int i = 0; i < 4; i++)
        tile[ty + i * 8][tx] = W[(size_t)(tap * DIM + k0 + ty + i * 8) * DIM + n0 + tx];
    __syncthreads();
    #pragma unroll
    for (int i = 0; i < 4; i++) {
        int n = n0 + ty + i * 8;
        float v = tile[tx][ty + i * 8];
        __nv_bfloat16 h = __float2bfloat16(v);
        __nv_bfloat16 l = __float2bfloat16(v - __bfloat162float(h));
        g_wcHi[layer][(size_t)(tap * DIM + n) * DIM + k0 + tx] = h;
        g_wcLo[layer][(size_t)(tap * DIM + n) * DIM + k0 + tx] = l;
    }
}
// merged LSTM weight prep: z in [0,4): dir = z&1, rec = z>>1. Both fp16 single.
__global__ void wprep_lstm_kernel(const float* __restrict__ Wf,
                                  const float* __restrict__ Wb)
{
    __shared__ float tile[32][33];
    const int tx = threadIdx.x, ty = threadIdx.y;
    const int k0 = blockIdx.x * 32, n0 = blockIdx.y * 32;
    const int dir = blockIdx.z & 1, rec = blockIdx.z >> 1;
    const float* W = dir ? Wb : Wf;
    const int krow0 = rec ? DIM : 0;
    #pragma unroll
    for (int i = 0; i < 4; i++)
        tile[ty + i * 8][tx] = W[(size_t)(krow0 + k0 + ty + i * 8) * GDIM + n0 + tx];
    __syncthreads();
    #pragma unroll
    for (int i = 0; i < 4; i++) {
        int n = n0 + ty + i * 8;
        __half v = __float2half_rn(tile[tx][ty + i * 8]);
        if (rec) g_wrHi[dir][(size_t)n * DIM + k0 + tx] = v;
        else     g_wgF16[dir][(size_t)n * DIM + k0 + tx] = v;
    }
}

// =================== embedding -> bf16 hi/lo =================================
__global__ void embed_kernel(const int* __restrict__ x, const float* __restrict__ ew)
{
    int m = blockIdx.x;
    int tok = x[m];
    int j = threadIdx.x;
    float4 v = ((const float4*)(ew + (size_t)tok * DIM))[j];
    float f[4] = {v.x, v.y, v.z, v.w};
    __nv_bfloat16 h[4], l[4];
    #pragma unroll
    for (int i = 0; i < 4; i++) {
        h[i] = __float2bfloat16(f[i]);
        l[i] = __float2bfloat16(f[i] - __bfloat162float(h[i]));
    }
    *(uint2*)(g_aHi + (size_t)m * DIM + j * 4) = *(uint2*)h;
    *(uint2*)(g_aLo + (size_t)m * DIM + j * 4) = *(uint2*)l;
}

// =================== bf16 mma.sync conv GEMM (R14 proven engine) ==============
// f16out: epilogue writes single fp16 (conv3 -> gates input) instead of bf16 pair
__global__ void __launch_bounds__(256, 2) mma_gemm_kernel(
    const __nv_bfloat16* __restrict__ Ahi, const __nv_bfloat16* __restrict__ Alo,
    const __nv_bfloat16* __restrict__ BwHi, const __nv_bfloat16* __restrict__ BwLo,
    int layer, int f16out,
    __nv_bfloat16* __restrict__ outHi, __nv_bfloat16* __restrict__ outLo)
{
    extern __shared__ char smem[];
    const int taps = 3;
    const int tid = threadIdx.x;
    const int lane = tid & 31, wid = tid >> 5;
    const int wm = wid & 3, wn = wid >> 2;
    const int m0 = blockIdx.x * 128, n0 = blockIdx.y * 128;
    const int t0 = m0 & (LSEQ - 1);
    const uint32_t sb = smem_to_u32(smem);

    const int off0  = 1;
    const int arows = 130;

    float acc[2][8][4];
    #pragma unroll
    for (int a = 0; a < 2; a++)
        #pragma unroll
        for (int b = 0; b < 8; b++)
            #pragma unroll
            for (int c = 0; c < 4; c++) acc[a][b][c] = 0.f;

    #define DO_COPY_A(SLICE) do { \
        const int _kb = (SLICE) << 6; \
        const int _tot = arows * 8; \
        for (int _i = tid; _i < _tot; _i += 256) { \
            int _r = _i >> 3, _c8 = (_i & 7) << 3; \
            uint32_t _off = (uint32_t)(_r * 128) + (((uint32_t)_c8 * 2) ^ (((uint32_t)_r & 7) << 4)); \
            uint4 _vh = make_uint4(0u,0u,0u,0u), _vl = _vh; \
            int _tl = t0 + _r - off0; \
            if (_tl >= 0 && _tl < LSEQ) { \
                size_t _ga = (size_t)(m0 + _r - off0) * DIM + _kb + _c8; \
                _vh = *(const uint4*)(Ahi + _ga); \
                _vl = *(const uint4*)(Alo + _ga); \
            } \
            *(uint4*)(smem + _off) = _vh; \
            *(uint4*)(smem + 16640 + _off) = _vl; \
        } \
    } while (0)

    #define DO_COPY_B(IDX, ST) do { \
        const int _sl = (IDX) / taps, _tp = (IDX) % taps; \
        const int _kb = _sl << 6; \
        const int _rbase = _tp * DIM + n0; \
        char* _bp = smem + 33280 + (ST) * 32768; \
        for (int _i = tid; _i < 1024; _i += 256) { \
            int _r = _i >> 3, _c8 = (_i & 7) << 3; \
            uint32_t _off = (uint32_t)(_r * 128) + (((uint32_t)_c8 * 2) ^ (((uint32_t)_r & 7) << 4)); \
            size_t _ga = (size_t)(_rbase + _r) * DIM + _kb + _c8; \
            *(uint4*)(_bp + _off) = *(const uint4*)(BwHi + _ga); \
            *(uint4*)(_bp + 16384 + _off) = *(const uint4*)(BwLo + _ga); \
        } \
    } while (0)

    const int NB = 24;
    DO_COPY_A(0);
    DO_COPY_B(0, 0);
    __syncthreads();

    for (int idx = 0; idx < NB; idx++) {
        const int tap = idx % taps;
        const int bsel = idx & 1;
        const bool lastTap = (tap == taps - 1);

        if (idx + 1 < NB) DO_COPY_B(idx + 1, bsel ^ 1);

        const uint32_t aHiB = sb;
        const uint32_t aLoB = sb + 16640;
        const uint32_t bHiB = sb + 33280 + (uint32_t)bsel * 32768;
        const uint32_t bLoB = bHiB + 16384;
        #pragma unroll
        for (int k16 = 0; k16 < 4; k16++) {
            const uint32_t colA = (uint32_t)(k16 * 32) + (((uint32_t)lane >> 4) << 4);
            const uint32_t colB = (uint32_t)(k16 * 32) + ((((uint32_t)lane >> 3) & 1) << 4);
            uint32_t afh[2][4], afl[2][4];
            #pragma unroll
            for (int mt = 0; mt < 2; mt++) {
                uint32_t row = (uint32_t)(wm * 32 + mt * 16 + (lane & 15) + tap);
                uint32_t ad = row * 128 + (colA ^ ((row & 7) << 4));
                LDSM_X4(afh[mt][0], afh[mt][1], afh[mt][2], afh[mt][3], aHiB + ad);
                LDSM_X4(afl[mt][0], afl[mt][1], afl[mt][2], afl[mt][3], aLoB + ad);
            }
            #pragma unroll
            for (int half = 0; half < 2; half++) {
                uint32_t bfh[4][2], bfl[4][2];
                #pragma unroll
                for (int np = 0; np < 2; np++) {
                    uint32_t row = (uint32_t)(wn * 64 + (half * 2 + np) * 16 +
                                              (((lane >> 4) << 3) | (lane & 7)));
                    uint32_t bd = row * 128 + (colB ^ ((row & 7) << 4));
                    LDSM_X4(bfh[2*np][0], bfh[2*np][1], bfh[2*np+1][0], bfh[2*np+1][1], bHiB + bd);
                    LDSM_X4(bfl[2*np][0], bfl[2*np][1], bfl[2*np+1][0], bfl[2*np+1][1], bLoB + bd);
                }
                #pragma unroll
                for (int mt = 0; mt < 2; mt++)
                    #pragma unroll
                    for (int nt = 0; nt < 4; nt++) {
                        float* ac = acc[mt][half * 4 + nt];
                        MMA16816(ac, afh[mt], bfh[nt]);
                        MMA16816(ac, afl[mt], bfh[nt]);
                        MMA16816(ac, afh[mt], bfl[nt]);
                    }
            }
        }
        __syncthreads();
        if (lastTap && idx + 1 < NB) {
            DO_COPY_A((idx + 1) / taps);
            __syncthreads();
        }
    }
    #undef DO_COPY_A
    #undef DO_COPY_B

    const int g  = lane >> 2;
    const int tg = lane & 3;
    #pragma unroll
    for (int mt = 0; mt < 2; mt++) {
        const int mlo = m0 + wm * 32 + mt * 16 + g;
        const int mhi = mlo + 8;
        #pragma unroll
        for (int nt = 0; nt < 8; nt++) {
            const int n = n0 + wn * 64 + nt * 8 + tg * 2;
            const float al0 = g_alpha[layer][n],     be0 = g_beta[layer][n];
            const float al1 = g_alpha[layer][n + 1], be1 = g_beta[layer][n + 1];
            float v00 = fmaxf(fmaf(acc[mt][nt][0], al0, be0), 0.f);
            float v01 = fmaxf(fmaf(acc[mt][nt][1], al1, be1), 0.f);
            float v10 = fmaxf(fmaf(acc[mt][nt][2], al0, be0), 0.f);
            float v11 = fmaxf(fmaf(acc[mt][nt][3], al1, be1), 0.f);
            if (f16out) {
                __half* o16 = (__half*)outHi;
                *(__half2*)(o16 + (size_t)mlo * DIM + n) = __floats2half2_rn(v00, v01);
                *(__half2*)(o16 + (size_t)mhi * DIM + n) = __floats2half2_rn(v10, v11);
            } else {
                __nv_bfloat16 h00 = __float2bfloat16(v00), h01 = __float2bfloat16(v01);
                __nv_bfloat16 h10 = __float2bfloat16(v10), h11 = __float2bfloat16(v11);
                __nv_bfloat16 l00 = __float2bfloat16(v00 - __bfloat162float(h00));
                __nv_bfloat16 l01 = __float2bfloat16(v01 - __bfloat162float(h01));
                __nv_bfloat16 l10 = __float2bfloat16(v10 - __bfloat162float(h10));
                __nv_bfloat16 l11 = __float2bfloat16(v11 - __bfloat162float(h11));
                __nv_bfloat162 ph0; ph0.x = h00; ph0.y = h01;
                __nv_bfloat162 ph1; ph1.x = h10; ph1.y = h11;
                __nv_bfloat162 pl0; pl0.x = l00; pl0.y = l01;
                __nv_bfloat162 pl1; pl1.x = l10; pl1.y = l11;
                *(__nv_bfloat162*)(outHi + (size_t)mlo * DIM + n) = ph0;
                *(__nv_bfloat162*)(outHi + (size_t)mhi * DIM + n) = ph1;
                *(__nv_bfloat162*)(outLo + (size_t)mlo * DIM + n) = pl0;
                *(__nv_bfloat162*)(outLo + (size_t)mhi * DIM + n) = pl1;
            }
        }
    }
}

// =================== single-fp16 gates GEMM ====================================
// D[(t,b),n] = A[(b,t)] @ W^T + bias; A fp16 [m][k], W fp16 [n][k]; 1 MMA term.
// Tile 128x128 bperm (rows = 32 b x 4 t), K=512 in 8 chunks, double-buffered.
__global__ void __launch_bounds__(256, 2) gates_f16_kernel(
    const __half* __restrict__ Ax, const __half* __restrict__ Bw,
    const float* __restrict__ biasA, const float* __restrict__ biasB,
    float* __restrict__ gout)
{
    extern __shared__ char smem[];
    const int tid = threadIdx.x;
    const int lane = tid & 31, wid = tid >> 5;
    const int wm = wid & 3, wn = wid >> 2;
    const int n0 = blockIdx.y * 128;
    const int tb4 = blockIdx.x * 4;
    const int dz = blockIdx.z;
    const uint32_t sb = smem_to_u32(smem);

    Bw   += (size_t)dz * GDIM * DIM;
    gout += (size_t)dz * MTOT * GDIM;
    const float* bias = dz ? biasB : biasA;

    float acc[2][8][4];
    #pragma unroll
    for (int a = 0; a < 2; a++)
        #pragma unroll
        for (int b = 0; b < 8; b++)
            #pragma unroll
            for (int c = 0; c < 4; c++) acc[a][b][c] = 0.f;

    // smem: A stages at 0/16384, B stages at 32768/49152
    #define G_COPY(SL, ST) do { \
        const int _kb = (SL) << 6; \
        char* _aP = smem + (ST) * 16384; \
        char* _bP = smem + 32768 + (ST) * 16384; \
        for (int _i = tid; _i < 1024; _i += 256) { \
            int _r = _i >> 3, _c8 = (_i & 7) << 3; \
            uint32_t _off = (uint32_t)(_r * 128) + (((uint32_t)_c8 * 2) ^ (((uint32_t)_r & 7) << 4)); \
            size_t _ga = (size_t)(((_r & 31) << 10) + tb4 + (_r >> 5)) * DIM + _kb + _c8; \
            *(uint4*)(_aP + _off) = *(const uint4*)(Ax + _ga); \
            size_t _gb = (size_t)(n0 + _r) * DIM + _kb + _c8; \
            *(uint4*)(_bP + _off) = *(const uint4*)(Bw + _gb); \
        } \
    } while (0)

    G_COPY(0, 0);
    __syncthreads();

    for (int cc = 0; cc < 8; cc++) {
        const int st = cc & 1;
        if (cc + 1 < 8) G_COPY(cc + 1, st ^ 1);

        const uint32_t aB = sb + (uint32_t)st * 16384;
        const uint32_t bB = sb + 32768 + (uint32_t)st * 16384;
        #pragma unroll
        for (int k16 = 0; k16 < 4; k16++) {
            const uint32_t colA = (uint32_t)(k16 * 32) + (((uint32_t)lane >> 4) << 4);
            const uint32_t colB = (uint32_t)(k16 * 32) + ((((uint32_t)lane >> 3) & 1) << 4);
            uint32_t af[2][4];
            #pragma unroll
            for (int mt = 0; mt < 2; mt++) {
                uint32_t row = (uint32_t)(wm * 32 + mt * 16 + (lane & 15));
                uint32_t ad = row * 128 + (colA ^ ((row & 7) << 4));
                LDSM_X4(af[mt][0], af[mt][1], af[mt][2], af[mt][3], aB + ad);
            }
            uint32_t bf[8][2];
            #pragma unroll
            for (int q = 0; q < 4; q++) {
                uint32_t row = (uint32_t)(wn * 64 + q * 16 +
                                          (((lane >> 4) << 3) | (lane & 7)));
                uint32_t bd = row * 128 + (colB ^ ((row & 7) << 4));
                LDSM_X4(bf[2*q][0], bf[2*q][1], bf[2*q+1][0], bf[2*q+1][1], bB + bd);
            }
            #pragma unroll
            for (int mt = 0; mt < 2; mt++)
                #pragma unroll
                for (int nt = 0; nt < 8; nt++)
                    MMAF16(acc[mt][nt], af[mt], bf[nt]);
        }
        __syncthreads();
    }
    #undef G_COPY

    // epilogue: +bias -> smem transpose -> coalesced gpre [(t*2048+n)*32+b]
    const int g  = lane >> 2;
    const int tg = lane & 3;
    float* tile = (float*)smem;
    #pragma unroll
    for (int mt = 0; mt < 2; mt++) {
        const int rlo = wm * 32 + mt * 16 + g;
        const int rhi = rlo + 8;
        #pragma unroll
        for (int nt = 0; nt < 8; nt++) {
            const int nl = wn * 64 + nt * 8 + tg * 2;
            const float b0 = bias[n0 + nl], b1 = bias[n0 + nl + 1];
            tile[rlo * 129 + nl    ] = acc[mt][nt][0] + b0;
            tile[rlo * 129 + nl + 1] = acc[mt][nt][1] + b1;
            tile[rhi * 129 + nl    ] = acc[mt][nt][2] + b0;
            tile[rhi * 129 + nl + 1] = acc[mt][nt][3] + b1;
        }
    }
    __syncthreads();
    for (int i = tid; i < 16384; i += 256) {
        int b_  = i & 31;
        int nl  = (i >> 5) & 127;
        int tt  = i >> 12;
        gout[((size_t)(tb4 + tt) * GDIM + n0 + nl) * 32 + b_] =
            tile[(tt * 32 + b_) * 129 + nl];
    }
}

// =================== persistent LSTM recurrence (R14 proven) ==================
#define R_WHI 0
#define R_A   33280
#define R_PART 66560                        // 8*32*33*4 = 33792
#define R_OBH  100352                       // float[288] = 1152
#define R_OBP  101504                       // ushort[288] = 576
#define R_SMEM 102080

__global__ void __launch_bounds__(256, 1) lstm_recur_kernel(
    const __half* __restrict__ wrHi,
    const int* __restrict__ lengths, const float* __restrict__ gpreAll,
    float* __restrict__ out)
{
    extern __shared__ char sm[];
    float* part = (float*)(sm + R_PART);
    float* obh  = (float*)(sm + R_OBH);
    unsigned short* obp16 = (unsigned short*)(sm + R_OBP);
    __shared__ int len_s[32];

    const int tid = threadIdx.x;
    const int lane = tid & 31, u = tid >> 5;        // u in [0,8)
    const int dir = blockIdx.x >> 6;
    const int dc  = (blockIdx.x & 63) << 3;
    const uint32_t sb = smem_to_u32(sm);
    const float* gpre = gpreAll + (size_t)dir * MTOT * GDIM;
    const __half* wHi = wrHi + (size_t)dir * GDIM * DIM;
    unsigned* barP = &g_bar[dir][0];

    for (int i = tid; i < 2048; i += 256) {
        int r = i >> 6, c16 = i & 63;
        int n = ((r >> 3) << 9) + dc + (r & 7);
        uint4 vh = *(const uint4*)(wHi + (size_t)n * DIM + c16 * 8);
        *(uint4*)(sm + R_WHI + r * 1040 + c16 * 16) = vh;
    }
    if (tid < 32) len_s[tid] = lengths[tid];
    if (tid < 32)
        ((uint4*)g_h16[0][dir])[tid * 64 + (dc >> 3)] = make_uint4(0u, 0u, 0u, 0u);
    __syncthreads();

    uint32_t wf[4][8];
    {
        const uint32_t rB = (uint32_t)(((lane >> 4) << 3) | (lane & 7));
        const uint32_t hB = (uint32_t)(((lane >> 3) & 1) << 4);
        #pragma unroll
        for (int i = 0; i < 4; i++) {
            int kk = u * 4 + i;
            uint32_t col = (uint32_t)(kk * 32) + hB;
            LDSM_X4(wf[i][0], wf[i][1], wf[i][2], wf[i][3], sb + R_WHI + rB * 1040 + col);
            LDSM_X4(wf[i][4], wf[i][5], wf[i][6], wf[i][7], sb + R_WHI + (rB + 16) * 1040 + col);
        }
    }
    const int lenb = len_s[lane];

    __syncthreads();
    if (tid == 0) {
        unsigned prev = bar_arrive_(barP);
        if (prev != 63u) bar_wait_(barP, 64u);
    }
    __syncthreads();

    const uint32_t rA = (uint32_t)(lane & 15);
    const uint32_t hA = (uint32_t)((lane >> 4) << 4);
    float cst = 0.f;

    float gp0, gp1, gp2, gp3;
    {
        const int t0_ = dir ? (LSEQ - 1) : 0;
        const float* gq = gpre + ((size_t)t0_ * GDIM + dc + u) * 32 + lane;
        gp0 = __ldg(gq);
        gp1 = __ldg(gq + (size_t)512 * 32);
        gp2 = __ldg(gq + (size_t)1024 * 32);
        gp3 = __ldg(gq + (size_t)1536 * 32);
    }

    for (int s = 0; s < LSEQ; s++) {
        const int t = dir ? (LSEQ - 1 - s) : s;
        const int p = s & 1;
        const unsigned tgt = 64u * (unsigned)(s + 2);

        float gn0 = 0.f, gn1 = 0.f, gn2 = 0.f, gn3 = 0.f;
        if (s + 1 < LSEQ) {
            const int tn = dir ? (LSEQ - 2 - s) : (s + 1);
            const float* gq = gpre + ((size_t)tn * GDIM + dc + u) * 32 + lane;
            gn0 = __ldg(gq);
            gn1 = __ldg(gq + (size_t)512 * 32);
            gn2 = __ldg(gq + (size_t)1024 * 32);
            gn3 = __ldg(gq + (size_t)1536 * 32);
        }

        {
            const uint4* hp = (const uint4*)g_h16[p][dir];
            #pragma unroll
            for (int i = 0; i < 8; i++) {
                int idx = i * 256 + tid;
                int b_ = idx >> 6, c = idx & 63;
                uint4 v = __ldcg(hp + idx);
                if (dir && t >= len_s[b_] - 1) v = make_uint4(0u, 0u, 0u, 0u);
                *(uint4*)(sm + R_A + b_ * 1040 + c * 16) = v;
            }
        }
        __syncthreads();                                 // (1)

        float acc[2][4][4];
        #pragma unroll
        for (int a = 0; a < 2; a++)
            #pragma unroll
            for (int b = 0; b < 4; b++)
                #pragma unroll
                for (int c = 0; c < 4; c++) acc[a][b][c] = 0.f;

        #pragma unroll
        for (int i = 0; i < 4; i++) {
            int kk = u * 4 + i;
            uint32_t col = (uint32_t)(kk * 32) + hA;
            uint32_t af0[4], af1[4];
            LDSM_X4(af0[0], af0[1], af0[2], af0[3], sb + R_A + rA * 1040 + col);
            LDSM_X4(af1[0], af1[1], af1[2], af1[3], sb + R_A + (rA + 16) * 1040 + col);
            #pragma unroll
            for (int nt = 0; nt < 4; nt++) {
                MMAF16(acc[0][nt], af0, &wf[i][nt * 2]);
                MMAF16(acc[1][nt], af1, &wf[i][nt * 2]);
            }
        }

        {
            int row = lane >> 2, colp = (lane & 3) * 2;
            #pragma unroll
            for (int mt = 0; mt < 2; mt++)
                #pragma unroll
                for (int nt = 0; nt < 4; nt++) {
                    float* p0 = part + (u * 32 + mt * 16 + row) * 33 + nt * 8 + colp;
                    p0[0] = acc[mt][nt][0]; p0[1] = acc[mt][nt][1];
                    float* p1 = part + (u * 32 + mt * 16 + row + 8) * 33 + nt * 8 + colp;
                    p1[0] = acc[mt][nt][2]; p1[1] = acc[mt][nt][3];
                }
        }
        __syncthreads();                                 // (2)

        {
            float s0 = 0.f, s1 = 0.f, s2 = 0.f, s3 = 0.f;
            #pragma unroll
            for (int w = 0; w < 8; w++) {
                const float* pr = part + (w * 32 + lane) * 33;
                s0 += pr[u]; s1 += pr[8 + u]; s2 += pr[16 + u]; s3 += pr[24 + u];
            }
            float iv = sigmoid_fast_(gp0 + s0);
            float gv = tanh_fast_(gp1 + s1);
            float fv = sigmoid_fast_(gp2 + s2 + 1.f);
            float ov = sigmoid_fast_(gp3 + s3);
            if (dir && t >= lenb - 1) cst = 0.f;
            cst = fv * cst + iv * gv;
            float hh = ov * tanh_fast_(cst);
            obh[lane * 9 + u] = hh;
            obp16[lane * 9 + u] = __half_as_ushort(__float2half_rn(hh));
        }
        gp0 = gn0; gp1 = gn1; gp2 = gn2; gp3 = gn3;
        __syncthreads();                                 // (3)

        unsigned sdone = 0u;
        if (tid < 32) {
            const unsigned short* sp = obp16 + tid * 9;
            uint4 o4;
            o4.x = (unsigned)sp[0] | ((unsigned)sp[1] << 16);
            o4.y = (unsigned)sp[2] | ((unsigned)sp[3] << 16);
            o4.z = (unsigned)sp[4] | ((unsigned)sp[5] << 16);
            o4.w = (unsigned)sp[6] | ((unsigned)sp[7] << 16);
            ((uint4*)g_h16[p ^ 1][dir])[tid * 64 + (dc >> 3)] = o4;
            __syncwarp();
            if (tid == 0) {
                unsigned prev = bar_arrive_(barP);
                sdone = (prev == tgt - 1u) ? 1u : 0u;
            }
        }
        {
            int b2 = tid >> 3, d2 = tid & 7;
            out[(((size_t)b2 << 10) + t) * 1024 + (dir << 9) + dc + d2] = obh[b2 * 9 + d2];
        }
        if (tid == 0 && !sdone) bar_wait_(barP, tgt);
        __syncthreads();                                 // (4)
    }
}

// =================== launch ===================================================
extern "C" void kernel_launch(void* const* d_in, const int* in_sizes, int n_in,
                              void* d_out, int out_size)
{
    (void)in_sizes; (void)n_in; (void)out_size;
    const int*   x        = (const int*)  d_in[0];
    const int*   lengths  = (const int*)  d_in[1];
    const float* embed_w  = (const float*)d_in[2];
    const float* c1w = (const float*)d_in[3];
    const float* c1b = (const float*)d_in[4];
    const float* c2w = (const float*)d_in[5];
    const float* c2b = (const float*)d_in[6];
    const float* c3w = (const float*)d_in[7];
    const float* c3b = (const float*)d_in[8];
    const float* wf  = (const float*)d_in[9];
    const float* bf  = (const float*)d_in[10];
    const float* wb  = (const float*)d_in[11];
    const float* bb  = (const float*)d_in[12];
    const float* s1 = (const float*)d_in[13]; const float* o1 = (const float*)d_in[14];
    const float* m1 = (const float*)d_in[15]; const float* v1 = (const float*)d_in[16];
    const float* s2 = (const float*)d_in[17]; const float* o2 = (const float*)d_in[18];
    const float* m2 = (const float*)d_in[19]; const float* v2 = (const float*)d_in[20];
    const float* s3 = (const float*)d_in[21]; const float* o3 = (const float*)d_in[22];
    const float* m3 = (const float*)d_in[23]; const float* v3 = (const float*)d_in[24];
    float* out = (float*)d_out;

    __nv_bfloat16 *aHi, *aLo, *bHi, *bLo, *wcH, *wcL;
    __half *wgF, *wrH;
    cudaGetSymbolAddress((void**)&aHi, g_aHi);
    cudaGetSymbolAddress((void**)&aLo, g_aLo);
    cudaGetSymbolAddress((void**)&bHi, g_bHi);
    cudaGetSymbolAddress((void**)&bLo, g_bLo);
    cudaGetSymbolAddress((void**)&wcH, g_wcHi);
    cudaGetSymbolAddress((void**)&wcL, g_wcLo);
    cudaGetSymbolAddress((void**)&wgF, g_wgF16);
    cudaGetSymbolAddress((void**)&wrH, g_wrHi);
    float* gpre;
    cudaGetSymbolAddress((void**)&gpre, g_gpre);

    const size_t WC = (size_t)3 * DIM * DIM;

    const int SMEM_CONV  = 33280 + 2 * 32768;     // 98816
    const int SMEM_GATES = 66048;                 // max(65536 staging, 128*129*4 epi)
    cudaFuncSetAttribute(mma_gemm_kernel,
                         cudaFuncAttributeMaxDynamicSharedMemorySize, SMEM_CONV);
    cudaFuncSetAttribute(gates_f16_kernel,
                         cudaFuncAttributeMaxDynamicSharedMemorySize, SMEM_GATES);
    cudaFuncSetAttribute(lstm_recur_kernel,
                         cudaFuncAttributeMaxDynamicSharedMemorySize, R_SMEM);

    dim3 gconv(MTOT / 128, DIM / 128, 1);
    dim3 ggate(MTOT / 128, GDIM / 128, 2);
    dim3 bwp(32, 8);
    dim3 gwc(DIM / 32, DIM / 32, 9);
    dim3 gwl(DIM / 32, GDIM / 32, 4);

    bar_reset_kernel<<<1, 512>>>();               // determinism across replays
    wprep_conv_kernel<<<gwc, bwp>>>(c1w, c2w, c3w);
    bnprep_kernel<<<1, 512>>>(c1b, s1, o1, m1, v1,
                              c2b, s2, o2, m2, v2,
                              c3b, s3, o3, m3, v3);
    embed_kernel<<<MTOT, 128>>>(x, embed_w);
    mma_gemm_kernel<<<gconv, 256, SMEM_CONV>>>(aHi, aLo, wcH + 0 * WC, wcL + 0 * WC,
        0, 0, bHi, bLo);
    mma_gemm_kernel<<<gconv, 256, SMEM_CONV>>>(bHi, bLo, wcH + 1 * WC, wcL + 1 * WC,
        1, 0, aHi, aLo);
    mma_gemm_kernel<<<gconv, 256, SMEM_CONV>>>(aHi, aLo, wcH + 2 * WC, wcL + 2 * WC,
        2, 1, bHi, nullptr);                       // conv3 -> fp16 into bHi
    wprep_lstm_kernel<<<gwl, bwp>>>(wf, wb);
    gates_f16_kernel<<<ggate, 256, SMEM_GATES>>>((const __half*)bHi, wgF,
        bf, bb, gpre);
    lstm_recur_kernel<<<128, 256, R_SMEM>>>(wrH, lengths, gpre, out);
}